// round 1
// baseline (speedup 1.0000x reference)
#include <cuda_runtime.h>
#include <cuda_bf16.h>
#include <math.h>

// Problem constants
#define BB 4
#define TT 2048
#define BT 8192      // B*T
#define DD 256
#define NN 8192
#define HH 4
#define MM 2048      // N/H
#define LL 6
#define VOCAB 256
#define EPS 1e-5f

// ---------------- scratch buffers (device globals, no allocations) --------
__device__ float g_v[BT * DD];
__device__ float g_R[BT * DD];
__device__ float g_a[BT * DD];
__device__ float g_aln[BT * DD];
__device__ float g_u[BT * DD];
__device__ float g_Y[(size_t)BT * NN];   // 256 MB

// ---------------- helpers --------------------------------------------------
__device__ __forceinline__ float warp_sum(float v) {
#pragma unroll
    for (int o = 16; o > 0; o >>= 1) v += __shfl_xor_sync(0xffffffffu, v, o);
    return v;
}

// ---------------- LayerNorm kernels (one row / block, 256 threads) ---------
__global__ void embed_ln_kernel(const int* __restrict__ idx,
                                const float* __restrict__ wte,
                                float* __restrict__ out) {
    __shared__ float sh[8];
    int row = blockIdx.x;
    int d = threadIdx.x;
    float x = wte[idx[row] * DD + d];
    int wid = d >> 5, lane = d & 31;
    float s = warp_sum(x);
    if (lane == 0) sh[wid] = s;
    __syncthreads();
    float tot = 0.f;
#pragma unroll
    for (int i = 0; i < 8; i++) tot += sh[i];
    float mu = tot * (1.f / 256.f);
    __syncthreads();
    float dx = x - mu;
    s = warp_sum(dx * dx);
    if (lane == 0) sh[wid] = s;
    __syncthreads();
    tot = 0.f;
#pragma unroll
    for (int i = 0; i < 8; i++) tot += sh[i];
    out[row * DD + d] = dx * rsqrtf(tot * (1.f / 256.f) + EPS);
}

__global__ void ln_kernel(const float* __restrict__ in, float* __restrict__ out) {
    __shared__ float sh[8];
    int row = blockIdx.x;
    int d = threadIdx.x;
    float x = in[row * DD + d];
    int wid = d >> 5, lane = d & 31;
    float s = warp_sum(x);
    if (lane == 0) sh[wid] = s;
    __syncthreads();
    float tot = 0.f;
#pragma unroll
    for (int i = 0; i < 8; i++) tot += sh[i];
    float mu = tot * (1.f / 256.f);
    __syncthreads();
    float dx = x - mu;
    s = warp_sum(dx * dx);
    if (lane == 0) sh[wid] = s;
    __syncthreads();
    tot = 0.f;
#pragma unroll
    for (int i = 0; i < 8; i++) tot += sh[i];
    out[row * DD + d] = dx * rsqrtf(tot * (1.f / 256.f) + EPS);
}

__global__ void ln_add_kernel(const float* __restrict__ in, float* __restrict__ v) {
    __shared__ float sh[8];
    int row = blockIdx.x;
    int d = threadIdx.x;
    float x = in[row * DD + d];
    int wid = d >> 5, lane = d & 31;
    float s = warp_sum(x);
    if (lane == 0) sh[wid] = s;
    __syncthreads();
    float tot = 0.f;
#pragma unroll
    for (int i = 0; i < 8; i++) tot += sh[i];
    float mu = tot * (1.f / 256.f);
    __syncthreads();
    float dx = x - mu;
    s = warp_sum(dx * dx);
    if (lane == 0) sh[wid] = s;
    __syncthreads();
    tot = 0.f;
#pragma unroll
    for (int i = 0; i < 8; i++) tot += sh[i];
    v[row * DD + d] += dx * rsqrtf(tot * (1.f / 256.f) + EPS);
}

// ---------------- RoPE: R = rope(v) ----------------------------------------
__global__ void rope_kernel(const float* __restrict__ v, float* __restrict__ R) {
    int row = blockIdx.x;
    int d = threadIdx.x;
    int t = row & (TT - 1);
    float x = v[row * DD + d];
    float xr = (d < 128) ? -v[row * DD + d + 128] : v[row * DD + d - 128];
    int j = d & 127;
    // inv_freq = 10000^(-2j/256) = exp(-(2j/256)*ln(10000))
    float inv = expf(-(float)j * (2.f / 256.f) * 9.210340371976184f);
    float ang = (float)t * inv;
    // accurate range reduction (fast-math-safe): r = ang mod 2*pi
    const float TWO_PI_HI = 6.28318548202514648f;
    const float TWO_PI_LO = -1.74845553e-7f;
    float k = rintf(ang * 0.15915494309189535f);
    float r = fmaf(-k, TWO_PI_HI, ang);
    r = fmaf(-k, TWO_PI_LO, r);
    float sn = sinf(r), cs = cosf(r);
    R[row * DD + d] = x * cs + xr * sn;
}

// ---------------- causal linear attention ----------------------------------
// a[b,t,:] = sum_{s<=t} (R[b,t] . R[b,s]) * v[b,s]
// grid: (T/64, B), 256 threads, dynamic smem: Q(64x264) + KV(64x264) + S(64x68)
#define ATTN_SMEM ((2 * 64 * 264 + 64 * 68) * 4)
__global__ void __launch_bounds__(256, 1)
attn_kernel(const float* __restrict__ Rg, const float* __restrict__ Vg,
            float* __restrict__ Ag) {
    extern __shared__ float sm[];
    float* Qs = sm;                   // 64 x 264
    float* Ks = sm + 64 * 264;        // 64 x 264  (K tile, then reused as V tile)
    float* Ss = sm + 2 * 64 * 264;    // 64 x 68

    int tb = blockIdx.x;
    int b = blockIdx.y;
    const float* Rb = Rg + b * TT * DD;
    const float* Vb = Vg + b * TT * DD;
    float* Ab = Ag + b * TT * DD;
    int tid = threadIdx.x;
    int q0 = tb * 64;

    // load Q tile (64 x 256 floats = 4096 float4)
    for (int l = tid; l < 4096; l += 256) {
        int r = l >> 6, c4 = l & 63;
        *(float4*)&Qs[r * 264 + c4 * 4] =
            *(const float4*)&Rb[(q0 + r) * DD + c4 * 4];
    }

    float acc[64];
#pragma unroll
    for (int i = 0; i < 64; i++) acc[i] = 0.f;

    int r = tid >> 2;            // output row / S row (0..63)
    int cg = tid & 3;            // column group for output (64 cols each)
    int sj0 = (tid & 3) * 16;    // S column group (16 cols each)

    for (int st = 0; st <= tb; st++) {
        int s0 = st * 64;
        __syncthreads();  // prior users of Ks / Ss done
        // load K tile
        for (int l = tid; l < 4096; l += 256) {
            int rr = l >> 6, c4 = l & 63;
            *(float4*)&Ks[rr * 264 + c4 * 4] =
                *(const float4*)&Rb[(s0 + rr) * DD + c4 * 4];
        }
        __syncthreads();
        // S = Q K^T  (each thread: row r, cols sj0..sj0+15)
        float sacc[16];
#pragma unroll
        for (int jj = 0; jj < 16; jj++) sacc[jj] = 0.f;
        for (int d4 = 0; d4 < 64; d4++) {
            float4 q = *(float4*)&Qs[r * 264 + d4 * 4];
#pragma unroll
            for (int jj = 0; jj < 16; jj++) {
                float4 kk = *(float4*)&Ks[(sj0 + jj) * 264 + d4 * 4];
                sacc[jj] += q.x * kk.x + q.y * kk.y + q.z * kk.z + q.w * kk.w;
            }
        }
        if (st == tb) {
#pragma unroll
            for (int jj = 0; jj < 16; jj++)
                if (sj0 + jj > r) sacc[jj] = 0.f;
        }
#pragma unroll
        for (int jj = 0; jj < 16; jj++) Ss[r * 68 + sj0 + jj] = sacc[jj];
        __syncthreads();
        // load V tile into Ks
        for (int l = tid; l < 4096; l += 256) {
            int rr = l >> 6, c4 = l & 63;
            *(float4*)&Ks[rr * 264 + c4 * 4] =
                *(const float4*)&Vb[(s0 + rr) * DD + c4 * 4];
        }
        __syncthreads();
        // acc += S @ V   (thread: row r, cols cg*64..cg*64+63)
        for (int k = 0; k < 64; k++) {
            float s = Ss[r * 68 + k];
#pragma unroll
            for (int j4 = 0; j4 < 16; j4++) {
                float4 vv = *(float4*)&Ks[k * 264 + cg * 64 + j4 * 4];
                acc[j4 * 4 + 0] = fmaf(s, vv.x, acc[j4 * 4 + 0]);
                acc[j4 * 4 + 1] = fmaf(s, vv.y, acc[j4 * 4 + 1]);
                acc[j4 * 4 + 2] = fmaf(s, vv.z, acc[j4 * 4 + 2]);
                acc[j4 * 4 + 3] = fmaf(s, vv.w, acc[j4 * 4 + 3]);
            }
        }
    }
#pragma unroll
    for (int j4 = 0; j4 < 16; j4++) {
        float4 o = make_float4(acc[j4 * 4 + 0], acc[j4 * 4 + 1],
                               acc[j4 * 4 + 2], acc[j4 * 4 + 3]);
        *(float4*)&Ab[(q0 + r) * DD + cg * 64 + j4 * 4] = o;
    }
}

// ---------------- fused x/y GEMM + relu-gate -------------------------------
// Y[bt, n] = relu(v[bt,:] . Wx[h,:,m]) * relu(aln[bt,:] . Wy[h,:,m]),  n=h*M+m
// grid: (N/64, BT/64), 256 threads, 4x4 micro-tile, K=256 in 16-chunks
__global__ void __launch_bounds__(256)
xy_kernel(const float* __restrict__ v, const float* __restrict__ aln,
          const float* __restrict__ Wx, const float* __restrict__ Wy,
          float* __restrict__ Y) {
    __shared__ float As[16][68];   // v tile, transposed  [k][i]
    __shared__ float A2s[16][68];  // aln tile, transposed
    __shared__ float Bxs[16][64];
    __shared__ float Bys[16][64];

    int col0 = blockIdx.x * 64;
    int row0 = blockIdx.y * 64;
    int h = col0 >> 11;          // / 2048
    int m0 = col0 & (MM - 1);
    const float* WxB = Wx + h * DD * MM;
    const float* WyB = Wy + h * DD * MM;

    int tid = threadIdx.x;
    int tx = tid & 15, ty = tid >> 4;

    float accx[4][4] = {};
    float accy[4][4] = {};

    int ak = tid & 15, ai0 = tid >> 4;
    int bj = tid & 63, bk = tid >> 6;

    for (int k0 = 0; k0 < DD; k0 += 16) {
        __syncthreads();
#pragma unroll
        for (int rr = 0; rr < 4; rr++) {
            int ar = row0 + ai0 + rr * 16;
            As[ak][ai0 + rr * 16] = v[ar * DD + k0 + ak];
            A2s[ak][ai0 + rr * 16] = aln[ar * DD + k0 + ak];
        }
#pragma unroll
        for (int rr = 0; rr < 4; rr++) {
            int kk = bk + rr * 4;
            Bxs[kk][bj] = WxB[(k0 + kk) * MM + m0 + bj];
            Bys[kk][bj] = WyB[(k0 + kk) * MM + m0 + bj];
        }
        __syncthreads();
#pragma unroll
        for (int k = 0; k < 16; k++) {
            float4 a4 = *(float4*)&As[k][ty * 4];
            float4 a24 = *(float4*)&A2s[k][ty * 4];
            float4 bx4 = *(float4*)&Bxs[k][tx * 4];
            float4 by4 = *(float4*)&Bys[k][tx * 4];
            float av[4] = {a4.x, a4.y, a4.z, a4.w};
            float a2v[4] = {a24.x, a24.y, a24.z, a24.w};
            float bxv[4] = {bx4.x, bx4.y, bx4.z, bx4.w};
            float byv[4] = {by4.x, by4.y, by4.z, by4.w};
#pragma unroll
            for (int i = 0; i < 4; i++)
#pragma unroll
                for (int j = 0; j < 4; j++) {
                    accx[i][j] = fmaf(av[i], bxv[j], accx[i][j]);
                    accy[i][j] = fmaf(a2v[i], byv[j], accy[i][j]);
                }
        }
    }
#pragma unroll
    for (int i = 0; i < 4; i++) {
        float4 o;
        o.x = fmaxf(accx[i][0], 0.f) * fmaxf(accy[i][0], 0.f);
        o.y = fmaxf(accx[i][1], 0.f) * fmaxf(accy[i][1], 0.f);
        o.z = fmaxf(accx[i][2], 0.f) * fmaxf(accy[i][2], 0.f);
        o.w = fmaxf(accx[i][3], 0.f) * fmaxf(accy[i][3], 0.f);
        *(float4*)&Y[(size_t)(row0 + ty * 4 + i) * NN + col0 + tx * 4] = o;
    }
}

// ---------------- generic 64x64 tiled GEMM  C = A @ B ----------------------
// A: [M,K] row-major lda, B: [K,N] row-major ldb, C: [M,N] ldc.
// grid: (N/64, M/64), 256 threads, 4x4 micro-tile.
__global__ void __launch_bounds__(256)
gemm64_kernel(const float* __restrict__ A, const float* __restrict__ B,
              float* __restrict__ C, int Kdim, int lda, int ldb, int ldc) {
    __shared__ float As[16][68];  // [k][i]
    __shared__ float Bs[16][64];  // [k][j]

    int col0 = blockIdx.x * 64;
    int row0 = blockIdx.y * 64;
    int tid = threadIdx.x;
    int tx = tid & 15, ty = tid >> 4;
    float acc[4][4] = {};

    int ak = tid & 15, ai0 = tid >> 4;
    int bj = tid & 63, bk = tid >> 6;

    for (int k0 = 0; k0 < Kdim; k0 += 16) {
        __syncthreads();
#pragma unroll
        for (int rr = 0; rr < 4; rr++)
            As[ak][ai0 + rr * 16] =
                A[(size_t)(row0 + ai0 + rr * 16) * lda + k0 + ak];
#pragma unroll
        for (int rr = 0; rr < 4; rr++) {
            int kk = bk + rr * 4;
            Bs[kk][bj] = B[(size_t)(k0 + kk) * ldb + col0 + bj];
        }
        __syncthreads();
#pragma unroll
        for (int k = 0; k < 16; k++) {
            float4 a4 = *(float4*)&As[k][ty * 4];
            float4 b4 = *(float4*)&Bs[k][tx * 4];
            float av[4] = {a4.x, a4.y, a4.z, a4.w};
            float bv[4] = {b4.x, b4.y, b4.z, b4.w};
#pragma unroll
            for (int i = 0; i < 4; i++)
#pragma unroll
                for (int j = 0; j < 4; j++)
                    acc[i][j] = fmaf(av[i], bv[j], acc[i][j]);
        }
    }
#pragma unroll
    for (int i = 0; i < 4; i++) {
        float4 o = make_float4(acc[i][0], acc[i][1], acc[i][2], acc[i][3]);
        *(float4*)&C[(size_t)(row0 + ty * 4 + i) * ldc + col0 + tx * 4] = o;
    }
}

// ---------------- launch ----------------------------------------------------
extern "C" void kernel_launch(void* const* d_in, const int* in_sizes, int n_in,
                              void* d_out, int out_size) {
    const int* idx = (const int*)d_in[0];
    const float* wte = (const float*)d_in[1];
    const float* encoder = (const float*)d_in[2];
    const float* dec_x = (const float*)d_in[3];
    const float* dec_y = (const float*)d_in[4];
    const float* readout = (const float*)d_in[5];
    float* out = (float*)d_out;

    float *pv, *pR, *pa, *paln, *pu, *pY;
    cudaGetSymbolAddress((void**)&pv, g_v);
    cudaGetSymbolAddress((void**)&pR, g_R);
    cudaGetSymbolAddress((void**)&pa, g_a);
    cudaGetSymbolAddress((void**)&paln, g_aln);
    cudaGetSymbolAddress((void**)&pu, g_u);
    cudaGetSymbolAddress((void**)&pY, g_Y);

    cudaFuncSetAttribute(attn_kernel,
                         cudaFuncAttributeMaxDynamicSharedMemorySize, ATTN_SMEM);

    // embed + LN
    embed_ln_kernel<<<BT, 256>>>(idx, wte, pv);

    for (int layer = 0; layer < LL; layer++) {
        rope_kernel<<<BT, 256>>>(pv, pR);
        attn_kernel<<<dim3(TT / 64, BB), 256, ATTN_SMEM>>>(pR, pv, pa);
        ln_kernel<<<BT, 256>>>(pa, paln);
        xy_kernel<<<dim3(NN / 64, BT / 64), 256>>>(pv, paln, dec_x, dec_y, pY);
        gemm64_kernel<<<dim3(DD / 64, BT / 64), 256>>>(pY, encoder, pu,
                                                       NN, NN, DD, DD);
        ln_add_kernel<<<BT, 256>>>(pu, pv);
    }

    // logits = v @ readout
    gemm64_kernel<<<dim3(VOCAB / 64, BT / 64), 256>>>(pv, readout, out,
                                                      DD, DD, VOCAB, VOCAB);
}

// round 4
// speedup vs baseline: 1.2998x; 1.2998x over previous
#include <cuda_runtime.h>
#include <cuda_bf16.h>
#include <math.h>
#include <stdint.h>

// Problem constants
#define BB 4
#define TT 2048
#define BT 8192      // B*T
#define DD 256
#define NN 8192
#define HH 4
#define MM 2048      // N/H
#define LL 6
#define VOCAB 256
#define EPS 1e-5f

// single dynamic-smem declaration shared by all kernels
extern __shared__ char dynsm[];

// ---------------- scratch buffers (device globals, no allocations) --------
__device__ float g_v[BT * DD];
__device__ float g_R[BT * DD];
__device__ float g_a[BT * DD];
__device__ float g_u[BT * DD];
__device__ __nv_bfloat16 g_vhi[BT * DD], g_vlo[BT * DD];
__device__ __nv_bfloat16 g_alnhi[BT * DD], g_alnlo[BT * DD];
__device__ __nv_bfloat16 g_wxhi[NN * DD], g_wxlo[NN * DD];
__device__ __nv_bfloat16 g_wyhi[NN * DD], g_wylo[NN * DD];
__device__ __nv_bfloat16 g_enchi[DD * NN], g_enclo[DD * NN];
__device__ __nv_bfloat16 g_rdhi[VOCAB * DD], g_rdlo[VOCAB * DD];
__device__ float g_X[(size_t)BT * NN];                       // 256 MB
__device__ __nv_bfloat16 g_Yhi[(size_t)BT * NN];             // 128 MB
__device__ __nv_bfloat16 g_Ylo[(size_t)BT * NN];             // 128 MB

// ---------------- PTX helpers ----------------------------------------------
__device__ __forceinline__ uint32_t smem_u32(const void* p) {
    uint32_t a;
    asm("{ .reg .u64 t; cvta.to.shared.u64 t, %1; cvt.u32.u64 %0, t; }"
        : "=r"(a) : "l"(p));
    return a;
}

#define LDSM_X4(r0, r1, r2, r3, addr) \
    asm volatile("ldmatrix.sync.aligned.m8n8.x4.shared.b16 {%0,%1,%2,%3}, [%4];" \
        : "=r"(r0), "=r"(r1), "=r"(r2), "=r"(r3) : "r"(addr))

#define MMA_BF16(d, a, b) \
    asm volatile( \
        "mma.sync.aligned.m16n8k16.row.col.f32.bf16.bf16.f32 " \
        "{%0,%1,%2,%3}, {%4,%5,%6,%7}, {%8,%9}, {%0,%1,%2,%3};" \
        : "+f"((d)[0]), "+f"((d)[1]), "+f"((d)[2]), "+f"((d)[3]) \
        : "r"((a)[0]), "r"((a)[1]), "r"((a)[2]), "r"((a)[3]), \
          "r"((b)[0]), "r"((b)[1]))

// ---------------- misc helpers ----------------------------------------------
__device__ __forceinline__ float warp_sum(float v) {
#pragma unroll
    for (int o = 16; o > 0; o >>= 1) v += __shfl_xor_sync(0xffffffffu, v, o);
    return v;
}
__device__ __forceinline__ void split2(float x, __nv_bfloat16& h, __nv_bfloat16& l) {
    __nv_bfloat16 hh = __float2bfloat16(x);
    h = hh;
    l = __float2bfloat16(x - __bfloat162float(hh));
}

// ---------------- weight conversion (transpose + bf16 split) ----------------
__global__ void conv_dec_kernel(const float* __restrict__ src,
                                __nv_bfloat16* __restrict__ hi,
                                __nv_bfloat16* __restrict__ lo) {
    size_t i = (size_t)blockIdx.x * 256 + threadIdx.x;   // over NN*DD, d fastest
    int d = (int)(i & 255);
    size_t n = i >> 8;
    int h = (int)(n >> 11);
    int m = (int)(n & 2047);
    float x = src[((size_t)h * DD + d) * MM + m];
    split2(x, hi[i], lo[i]);
}
__global__ void conv_enc_kernel(const float* __restrict__ src,
                                __nv_bfloat16* __restrict__ hi,
                                __nv_bfloat16* __restrict__ lo) {
    size_t i = (size_t)blockIdx.x * 256 + threadIdx.x;   // over DD*NN, n fastest
    int n = (int)(i & 8191);
    int d = (int)(i >> 13);
    float x = src[(size_t)n * DD + d];
    split2(x, hi[i], lo[i]);
}
__global__ void conv_rd_kernel(const float* __restrict__ src,
                               __nv_bfloat16* __restrict__ hi,
                               __nv_bfloat16* __restrict__ lo) {
    size_t i = (size_t)blockIdx.x * 256 + threadIdx.x;   // over VOCAB*DD, d fastest
    int d = (int)(i & 255);
    int v = (int)(i >> 8);
    float x = src[(size_t)d * VOCAB + v];
    split2(x, hi[i], lo[i]);
}

// ---------------- LayerNorm kernels (one row / block, 256 threads) ---------
__global__ void embed_ln_kernel(const int* __restrict__ idx,
                                const float* __restrict__ wte,
                                float* __restrict__ out,
                                __nv_bfloat16* __restrict__ ohi,
                                __nv_bfloat16* __restrict__ olo) {
    __shared__ float sh[8];
    int row = blockIdx.x;
    int d = threadIdx.x;
    float x = wte[idx[row] * DD + d];
    int wid = d >> 5, lane = d & 31;
    float s = warp_sum(x);
    if (lane == 0) sh[wid] = s;
    __syncthreads();
    float tot = 0.f;
#pragma unroll
    for (int i = 0; i < 8; i++) tot += sh[i];
    float mu = tot * (1.f / 256.f);
    __syncthreads();
    float dx = x - mu;
    s = warp_sum(dx * dx);
    if (lane == 0) sh[wid] = s;
    __syncthreads();
    tot = 0.f;
#pragma unroll
    for (int i = 0; i < 8; i++) tot += sh[i];
    float r = dx * rsqrtf(tot * (1.f / 256.f) + EPS);
    out[row * DD + d] = r;
    split2(r, ohi[row * DD + d], olo[row * DD + d]);
}

__global__ void ln_split_kernel(const float* __restrict__ in,
                                __nv_bfloat16* __restrict__ ohi,
                                __nv_bfloat16* __restrict__ olo) {
    __shared__ float sh[8];
    int row = blockIdx.x;
    int d = threadIdx.x;
    float x = in[row * DD + d];
    int wid = d >> 5, lane = d & 31;
    float s = warp_sum(x);
    if (lane == 0) sh[wid] = s;
    __syncthreads();
    float tot = 0.f;
#pragma unroll
    for (int i = 0; i < 8; i++) tot += sh[i];
    float mu = tot * (1.f / 256.f);
    __syncthreads();
    float dx = x - mu;
    s = warp_sum(dx * dx);
    if (lane == 0) sh[wid] = s;
    __syncthreads();
    tot = 0.f;
#pragma unroll
    for (int i = 0; i < 8; i++) tot += sh[i];
    float r = dx * rsqrtf(tot * (1.f / 256.f) + EPS);
    split2(r, ohi[row * DD + d], olo[row * DD + d]);
}

__global__ void ln_add_kernel(const float* __restrict__ in,
                              float* __restrict__ v,
                              __nv_bfloat16* __restrict__ vhi,
                              __nv_bfloat16* __restrict__ vlo) {
    __shared__ float sh[8];
    int row = blockIdx.x;
    int d = threadIdx.x;
    float x = in[row * DD + d];
    int wid = d >> 5, lane = d & 31;
    float s = warp_sum(x);
    if (lane == 0) sh[wid] = s;
    __syncthreads();
    float tot = 0.f;
#pragma unroll
    for (int i = 0; i < 8; i++) tot += sh[i];
    float mu = tot * (1.f / 256.f);
    __syncthreads();
    float dx = x - mu;
    s = warp_sum(dx * dx);
    if (lane == 0) sh[wid] = s;
    __syncthreads();
    tot = 0.f;
#pragma unroll
    for (int i = 0; i < 8; i++) tot += sh[i];
    float nv = v[row * DD + d] + dx * rsqrtf(tot * (1.f / 256.f) + EPS);
    v[row * DD + d] = nv;
    split2(nv, vhi[row * DD + d], vlo[row * DD + d]);
}

// ---------------- RoPE: R = rope(v) ----------------------------------------
__global__ void rope_kernel(const float* __restrict__ v, float* __restrict__ R) {
    int row = blockIdx.x;
    int d = threadIdx.x;
    int t = row & (TT - 1);
    float x = v[row * DD + d];
    float xr = (d < 128) ? -v[row * DD + d + 128] : v[row * DD + d - 128];
    int j = d & 127;
    float inv = expf(-(float)j * (2.f / 256.f) * 9.210340371976184f);
    float ang = (float)t * inv;
    const float TWO_PI_HI = 6.28318548202514648f;
    const float TWO_PI_LO = -1.74845553e-7f;
    float k = rintf(ang * 0.15915494309189535f);
    float r = fmaf(-k, TWO_PI_HI, ang);
    r = fmaf(-k, TWO_PI_LO, r);
    float sn = sinf(r), cs = cosf(r);
    R[row * DD + d] = x * cs + xr * sn;
}

// ---------------- causal linear attention (fp32 SIMT) ----------------------
#define ATTN_SMEM ((2 * 64 * 264 + 64 * 68) * 4)
__global__ void __launch_bounds__(256, 1)
attn_kernel(const float* __restrict__ Rg, const float* __restrict__ Vg,
            float* __restrict__ Ag) {
    float* smf = (float*)dynsm;
    float* Qs = smf;
    float* Ks = smf + 64 * 264;
    float* Ss = smf + 2 * 64 * 264;

    int tb = blockIdx.x;
    int b = blockIdx.y;
    const float* Rb = Rg + b * TT * DD;
    const float* Vb = Vg + b * TT * DD;
    float* Ab = Ag + b * TT * DD;
    int tid = threadIdx.x;
    int q0 = tb * 64;

    for (int l = tid; l < 4096; l += 256) {
        int r = l >> 6, c4 = l & 63;
        *(float4*)&Qs[r * 264 + c4 * 4] =
            *(const float4*)&Rb[(q0 + r) * DD + c4 * 4];
    }

    float acc[64];
#pragma unroll
    for (int i = 0; i < 64; i++) acc[i] = 0.f;

    int r = tid >> 2;
    int cg = tid & 3;
    int sj0 = (tid & 3) * 16;

    for (int st = 0; st <= tb; st++) {
        int s0 = st * 64;
        __syncthreads();
        for (int l = tid; l < 4096; l += 256) {
            int rr = l >> 6, c4 = l & 63;
            *(float4*)&Ks[rr * 264 + c4 * 4] =
                *(const float4*)&Rb[(s0 + rr) * DD + c4 * 4];
        }
        __syncthreads();
        float sacc[16];
#pragma unroll
        for (int jj = 0; jj < 16; jj++) sacc[jj] = 0.f;
        for (int d4 = 0; d4 < 64; d4++) {
            float4 q = *(float4*)&Qs[r * 264 + d4 * 4];
#pragma unroll
            for (int jj = 0; jj < 16; jj++) {
                float4 kk = *(float4*)&Ks[(sj0 + jj) * 264 + d4 * 4];
                sacc[jj] += q.x * kk.x + q.y * kk.y + q.z * kk.z + q.w * kk.w;
            }
        }
        if (st == tb) {
#pragma unroll
            for (int jj = 0; jj < 16; jj++)
                if (sj0 + jj > r) sacc[jj] = 0.f;
        }
#pragma unroll
        for (int jj = 0; jj < 16; jj++) Ss[r * 68 + sj0 + jj] = sacc[jj];
        __syncthreads();
        for (int l = tid; l < 4096; l += 256) {
            int rr = l >> 6, c4 = l & 63;
            *(float4*)&Ks[rr * 264 + c4 * 4] =
                *(const float4*)&Vb[(s0 + rr) * DD + c4 * 4];
        }
        __syncthreads();
        for (int k = 0; k < 64; k++) {
            float s = Ss[r * 68 + k];
#pragma unroll
            for (int j4 = 0; j4 < 16; j4++) {
                float4 vv = *(float4*)&Ks[k * 264 + cg * 64 + j4 * 4];
                acc[j4 * 4 + 0] = fmaf(s, vv.x, acc[j4 * 4 + 0]);
                acc[j4 * 4 + 1] = fmaf(s, vv.y, acc[j4 * 4 + 1]);
                acc[j4 * 4 + 2] = fmaf(s, vv.z, acc[j4 * 4 + 2]);
                acc[j4 * 4 + 3] = fmaf(s, vv.w, acc[j4 * 4 + 3]);
            }
        }
    }
#pragma unroll
    for (int j4 = 0; j4 < 16; j4++) {
        float4 o = make_float4(acc[j4 * 4 + 0], acc[j4 * 4 + 1],
                               acc[j4 * 4 + 2], acc[j4 * 4 + 3]);
        *(float4*)&Ab[(q0 + r) * DD + cg * 64 + j4 * 4] = o;
    }
}

// ---------------- HMMA GEMM (mma.sync bf16, 2-term split) -------------------
// C[M x N] = A @ B^T :  A (hi,lo): [M x K] k-major,  B (hi,lo): [N x K] k-major.
// CTA tile 128x128, 8 warps (4m x 2n), warp tile 32x64, K-chunk 64.
// mode 0: C[row*ldc+col] = acc (fp32)
// mode 2: g = relu(gate[row*NN+col]) * relu(acc); split -> Ohi/Olo [M x NN]
#define TILE_B 18432                      // 128 rows * 144 bytes
#define TCG_SMEM (4 * TILE_B)
__global__ void __launch_bounds__(256)
tc_gemm(const __nv_bfloat16* __restrict__ Ahi, const __nv_bfloat16* __restrict__ Alo,
        const __nv_bfloat16* __restrict__ Bhi, const __nv_bfloat16* __restrict__ Blo,
        int K, int mode,
        float* __restrict__ C, int ldc,
        const float* __restrict__ gate,
        __nv_bfloat16* __restrict__ Ohi, __nv_bfloat16* __restrict__ Olo) {
    char* smc = dynsm;
    uint32_t sb = smem_u32(smc);
    const uint32_t sAhi = sb, sBhi = sb + 2 * TILE_B;

    int tid = threadIdx.x;
    int wid = tid >> 5;
    int lane = tid & 31;
    int warp_m = wid & 3;     // 0..3  (rows, 32 each)
    int warp_n = wid >> 2;    // 0..1  (cols, 64 each)

    int m0 = blockIdx.y * 128;
    int n0 = blockIdx.x * 128;

    float acc[2][8][4];
#pragma unroll
    for (int mt = 0; mt < 2; mt++)
#pragma unroll
        for (int nt = 0; nt < 8; nt++)
#pragma unroll
            for (int q = 0; q < 4; q++) acc[mt][nt][q] = 0.f;

    // ldmatrix lane addressing (within warp)
    uint32_t a_row_l = (uint32_t)(lane & 15);
    uint32_t a_col_l = (uint32_t)((lane >> 4) << 3);       // 0 or 8
    uint32_t b_row_l = (uint32_t)(((lane & 16) >> 1) + (lane & 7)); // +8 if lane>=16
    uint32_t b_col_l = (uint32_t)(lane & 8);               // 0 or 8

    int nchunks = K >> 6;
    for (int ch = 0; ch < nchunks; ch++) {
        int kc = ch << 6;
        __syncthreads();
        // load 4 tiles (128 x 64 bf16 each), row pad to 144B
#pragma unroll
        for (int l = tid; l < 1024; l += 256) {
            int r = l >> 3, c = l & 7;
            size_t ga = (size_t)(m0 + r) * K + kc + c * 8;
            size_t gb = (size_t)(n0 + r) * K + kc + c * 8;
            uint32_t so = (uint32_t)(r * 144 + c * 16);
            *(uint4*)(smc + 0 * TILE_B + so) = *(const uint4*)(Ahi + ga);
            *(uint4*)(smc + 1 * TILE_B + so) = *(const uint4*)(Alo + ga);
            *(uint4*)(smc + 2 * TILE_B + so) = *(const uint4*)(Bhi + gb);
            *(uint4*)(smc + 3 * TILE_B + so) = *(const uint4*)(Blo + gb);
        }
        __syncthreads();

#pragma unroll
        for (int ks = 0; ks < 4; ks++) {
            uint32_t ah[2][4], al[2][4];
#pragma unroll
            for (int mt = 0; mt < 2; mt++) {
                uint32_t row = (uint32_t)(warp_m * 32 + mt * 16) + a_row_l;
                uint32_t colb = ((uint32_t)(ks * 16) + a_col_l) * 2;
                uint32_t ad = sAhi + row * 144 + colb;
                LDSM_X4(ah[mt][0], ah[mt][1], ah[mt][2], ah[mt][3], ad);
                LDSM_X4(al[mt][0], al[mt][1], al[mt][2], al[mt][3], ad + TILE_B);
            }
            uint32_t bh[8][2], bl[8][2];
#pragma unroll
            for (int p = 0; p < 4; p++) {
                uint32_t row = (uint32_t)(warp_n * 64 + p * 16) + b_row_l;
                uint32_t colb = ((uint32_t)(ks * 16) + b_col_l) * 2;
                uint32_t bd = sBhi + row * 144 + colb;
                uint32_t q0, q1, q2, q3;
                LDSM_X4(q0, q1, q2, q3, bd);
                bh[2 * p][0] = q0; bh[2 * p][1] = q1;
                bh[2 * p + 1][0] = q2; bh[2 * p + 1][1] = q3;
                LDSM_X4(q0, q1, q2, q3, bd + TILE_B);
                bl[2 * p][0] = q0; bl[2 * p][1] = q1;
                bl[2 * p + 1][0] = q2; bl[2 * p + 1][1] = q3;
            }
            // product-major order: each accumulator revisited every 16 MMAs
#pragma unroll
            for (int mt = 0; mt < 2; mt++)
#pragma unroll
                for (int nt = 0; nt < 8; nt++)
                    MMA_BF16(acc[mt][nt], ah[mt], bh[nt]);
#pragma unroll
            for (int mt = 0; mt < 2; mt++)
#pragma unroll
                for (int nt = 0; nt < 8; nt++)
                    MMA_BF16(acc[mt][nt], ah[mt], bl[nt]);
#pragma unroll
            for (int mt = 0; mt < 2; mt++)
#pragma unroll
                for (int nt = 0; nt < 8; nt++)
                    MMA_BF16(acc[mt][nt], al[mt], bh[nt]);
        }
    }

    // epilogue (register fragments -> gmem)
    int tr = lane >> 2;
    int tc = (lane & 3) * 2;
    if (mode == 0) {
#pragma unroll
        for (int mt = 0; mt < 2; mt++) {
            int row = m0 + warp_m * 32 + mt * 16 + tr;
#pragma unroll
            for (int nt = 0; nt < 8; nt++) {
                int col = n0 + warp_n * 64 + nt * 8 + tc;
                float2 v0 = make_float2(acc[mt][nt][0], acc[mt][nt][1]);
                float2 v1 = make_float2(acc[mt][nt][2], acc[mt][nt][3]);
                *(float2*)&C[(size_t)row * ldc + col] = v0;
                *(float2*)&C[(size_t)(row + 8) * ldc + col] = v1;
            }
        }
    } else {
#pragma unroll
        for (int mt = 0; mt < 2; mt++) {
            int row = m0 + warp_m * 32 + mt * 16 + tr;
#pragma unroll
            for (int nt = 0; nt < 8; nt++) {
                int col = n0 + warp_n * 64 + nt * 8 + tc;
                size_t i0 = (size_t)row * NN + col;
                size_t i1 = (size_t)(row + 8) * NN + col;
                float2 gt0 = *(const float2*)&gate[i0];
                float2 gt1 = *(const float2*)&gate[i1];
                float g0 = fmaxf(acc[mt][nt][0], 0.f) * fmaxf(gt0.x, 0.f);
                float g1 = fmaxf(acc[mt][nt][1], 0.f) * fmaxf(gt0.y, 0.f);
                float g2 = fmaxf(acc[mt][nt][2], 0.f) * fmaxf(gt1.x, 0.f);
                float g3 = fmaxf(acc[mt][nt][3], 0.f) * fmaxf(gt1.y, 0.f);
                __nv_bfloat16 h0, l0, h1, l1, h2, l2, h3, l3;
                split2(g0, h0, l0);
                split2(g1, h1, l1);
                split2(g2, h2, l2);
                split2(g3, h3, l3);
                *(__nv_bfloat162*)(Ohi + i0) = __halves2bfloat162(h0, h1);
                *(__nv_bfloat162*)(Olo + i0) = __halves2bfloat162(l0, l1);
                *(__nv_bfloat162*)(Ohi + i1) = __halves2bfloat162(h2, h3);
                *(__nv_bfloat162*)(Olo + i1) = __halves2bfloat162(l2, l3);
            }
        }
    }
}

// ---------------- launch -----------------------------------------------------
extern "C" void kernel_launch(void* const* d_in, const int* in_sizes, int n_in,
                              void* d_out, int out_size) {
    const int* idx = (const int*)d_in[0];
    const float* wte = (const float*)d_in[1];
    const float* encoder = (const float*)d_in[2];
    const float* dec_x = (const float*)d_in[3];
    const float* dec_y = (const float*)d_in[4];
    const float* readout = (const float*)d_in[5];
    float* out = (float*)d_out;

    float *pv, *pR, *pa, *pu, *pX;
    __nv_bfloat16 *pvhi, *pvlo, *palnhi, *palnlo;
    __nv_bfloat16 *pwxhi, *pwxlo, *pwyhi, *pwylo, *penchi, *penclo, *prdhi, *prdlo;
    __nv_bfloat16 *pYhi, *pYlo;
    cudaGetSymbolAddress((void**)&pv, g_v);
    cudaGetSymbolAddress((void**)&pR, g_R);
    cudaGetSymbolAddress((void**)&pa, g_a);
    cudaGetSymbolAddress((void**)&pu, g_u);
    cudaGetSymbolAddress((void**)&pX, g_X);
    cudaGetSymbolAddress((void**)&pvhi, g_vhi);
    cudaGetSymbolAddress((void**)&pvlo, g_vlo);
    cudaGetSymbolAddress((void**)&palnhi, g_alnhi);
    cudaGetSymbolAddress((void**)&palnlo, g_alnlo);
    cudaGetSymbolAddress((void**)&pwxhi, g_wxhi);
    cudaGetSymbolAddress((void**)&pwxlo, g_wxlo);
    cudaGetSymbolAddress((void**)&pwyhi, g_wyhi);
    cudaGetSymbolAddress((void**)&pwylo, g_wylo);
    cudaGetSymbolAddress((void**)&penchi, g_enchi);
    cudaGetSymbolAddress((void**)&penclo, g_enclo);
    cudaGetSymbolAddress((void**)&prdhi, g_rdhi);
    cudaGetSymbolAddress((void**)&prdlo, g_rdlo);
    cudaGetSymbolAddress((void**)&pYhi, g_Yhi);
    cudaGetSymbolAddress((void**)&pYlo, g_Ylo);

    cudaFuncSetAttribute(attn_kernel,
                         cudaFuncAttributeMaxDynamicSharedMemorySize, ATTN_SMEM);
    cudaFuncSetAttribute(tc_gemm,
                         cudaFuncAttributeMaxDynamicSharedMemorySize, TCG_SMEM);

    // one-time per-launch weight conversion (transpose + bf16 split)
    conv_dec_kernel<<<(NN * DD) / 256, 256>>>(dec_x, pwxhi, pwxlo);
    conv_dec_kernel<<<(NN * DD) / 256, 256>>>(dec_y, pwyhi, pwylo);
    conv_enc_kernel<<<(DD * NN) / 256, 256>>>(encoder, penchi, penclo);
    conv_rd_kernel<<<(VOCAB * DD) / 256, 256>>>(readout, prdhi, prdlo);

    embed_ln_kernel<<<BT, 256>>>(idx, wte, pv, pvhi, pvlo);

    for (int layer = 0; layer < LL; layer++) {
        rope_kernel<<<BT, 256>>>(pv, pR);
        attn_kernel<<<dim3(TT / 64, BB), 256, ATTN_SMEM>>>(pR, pv, pa);
        ln_split_kernel<<<BT, 256>>>(pa, palnhi, palnlo);
        // X = v @ Wx^T  (fp32 out)
        tc_gemm<<<dim3(NN / 128, BT / 128), 256, TCG_SMEM>>>(
            pvhi, pvlo, pwxhi, pwxlo, DD, 0, pX, NN, nullptr, nullptr, nullptr);
        // Y = relu(aln @ Wy^T) * relu(X), split to bf16
        tc_gemm<<<dim3(NN / 128, BT / 128), 256, TCG_SMEM>>>(
            palnhi, palnlo, pwyhi, pwylo, DD, 2, nullptr, 0, pX, pYhi, pYlo);
        // u = Y @ encoder  (K = 8192, N = 256)
        tc_gemm<<<dim3(DD / 128, BT / 128), 256, TCG_SMEM>>>(
            pYhi, pYlo, penchi, penclo, NN, 0, pu, DD, nullptr, nullptr, nullptr);
        ln_add_kernel<<<BT, 256>>>(pu, pv, pvhi, pvlo);
    }

    // logits = v @ readout  (N = 256)
    tc_gemm<<<dim3(VOCAB / 128, BT / 128), 256, TCG_SMEM>>>(
        pvhi, pvlo, prdhi, prdlo, DD, 0, out, VOCAB, nullptr, nullptr, nullptr);
}

// round 5
// speedup vs baseline: 6.3645x; 4.8966x over previous
#include <cuda_runtime.h>
#include <cuda_bf16.h>
#include <math.h>
#include <stdint.h>

// Problem constants
#define BB 4
#define TT 2048
#define BT 8192      // B*T
#define DD 256
#define NN 8192
#define HH 4
#define MM 2048      // N/H
#define LL 6
#define VOCAB 256
#define EPS 1e-5f

// single dynamic-smem declaration shared by all kernels
extern __shared__ char dynsm[];

// ---------------- scratch buffers (device globals, no allocations) --------
__device__ float g_v[BT * DD];
__device__ float g_R[BT * DD];
__device__ float g_a[BT * DD];
__device__ float g_u[BT * DD];
__device__ __nv_bfloat16 g_vhi[BT * DD], g_vlo[BT * DD];
__device__ __nv_bfloat16 g_Rhi[BT * DD], g_Rlo[BT * DD];
__device__ __nv_bfloat16 g_alnhi[BT * DD], g_alnlo[BT * DD];
__device__ __nv_bfloat16 g_wxhi[NN * DD], g_wxlo[NN * DD];
__device__ __nv_bfloat16 g_wyhi[NN * DD], g_wylo[NN * DD];
__device__ __nv_bfloat16 g_enchi[DD * NN], g_enclo[DD * NN];
__device__ __nv_bfloat16 g_rdhi[VOCAB * DD], g_rdlo[VOCAB * DD];
__device__ float g_X[(size_t)BT * NN];                       // 256 MB
__device__ __nv_bfloat16 g_Yhi[(size_t)BT * NN];             // 128 MB
__device__ __nv_bfloat16 g_Ylo[(size_t)BT * NN];             // 128 MB
// linear-attention scratch
__device__ __nv_bfloat16 g_RThi[BB * DD * TT], g_RTlo[BB * DD * TT];  // [b][d][t]
__device__ __nv_bfloat16 g_VThi[BB * DD * TT], g_VTlo[BB * DD * TT];  // [b][e][t]
__device__ float g_H[(size_t)BB * 32 * DD * DD];                      // 33.5 MB
__device__ __nv_bfloat16 g_Mhi[(size_t)BB * 32 * DD * DD];            // 16.7 MB
__device__ __nv_bfloat16 g_Mlo[(size_t)BB * 32 * DD * DD];

// ---------------- PTX helpers ----------------------------------------------
__device__ __forceinline__ uint32_t smem_u32(const void* p) {
    uint32_t a;
    asm("{ .reg .u64 t; cvta.to.shared.u64 t, %1; cvt.u32.u64 %0, t; }"
        : "=r"(a) : "l"(p));
    return a;
}

#define LDSM_X4(r0, r1, r2, r3, addr) \
    asm volatile("ldmatrix.sync.aligned.m8n8.x4.shared.b16 {%0,%1,%2,%3}, [%4];" \
        : "=r"(r0), "=r"(r1), "=r"(r2), "=r"(r3) : "r"(addr))

#define MMA_BF16(d, a, b) \
    asm volatile( \
        "mma.sync.aligned.m16n8k16.row.col.f32.bf16.bf16.f32 " \
        "{%0,%1,%2,%3}, {%4,%5,%6,%7}, {%8,%9}, {%0,%1,%2,%3};" \
        : "+f"((d)[0]), "+f"((d)[1]), "+f"((d)[2]), "+f"((d)[3]) \
        : "r"((a)[0]), "r"((a)[1]), "r"((a)[2]), "r"((a)[3]), \
          "r"((b)[0]), "r"((b)[1]))

#define CP_ASYNC16(dst, src) \
    asm volatile("cp.async.cg.shared.global [%0], [%1], 16;" \
        :: "r"(dst), "l"(src) : "memory")
#define CP_COMMIT() asm volatile("cp.async.commit_group;" ::: "memory")
#define CP_WAIT(N)  asm volatile("cp.async.wait_group %0;" :: "n"(N) : "memory")

// ---------------- misc helpers ----------------------------------------------
__device__ __forceinline__ float warp_sum(float v) {
#pragma unroll
    for (int o = 16; o > 0; o >>= 1) v += __shfl_xor_sync(0xffffffffu, v, o);
    return v;
}
__device__ __forceinline__ void split2(float x, __nv_bfloat16& h, __nv_bfloat16& l) {
    __nv_bfloat16 hh = __float2bfloat16(x);
    h = hh;
    l = __float2bfloat16(x - __bfloat162float(hh));
}

// ---------------- weight conversion (transpose + bf16 split) ----------------
__global__ void conv_dec_kernel(const float* __restrict__ src,
                                __nv_bfloat16* __restrict__ hi,
                                __nv_bfloat16* __restrict__ lo) {
    size_t i = (size_t)blockIdx.x * 256 + threadIdx.x;
    int d = (int)(i & 255);
    size_t n = i >> 8;
    int h = (int)(n >> 11);
    int m = (int)(n & 2047);
    float x = src[((size_t)h * DD + d) * MM + m];
    split2(x, hi[i], lo[i]);
}
__global__ void conv_enc_kernel(const float* __restrict__ src,
                                __nv_bfloat16* __restrict__ hi,
                                __nv_bfloat16* __restrict__ lo) {
    size_t i = (size_t)blockIdx.x * 256 + threadIdx.x;
    int n = (int)(i & 8191);
    int d = (int)(i >> 13);
    float x = src[(size_t)n * DD + d];
    split2(x, hi[i], lo[i]);
}
__global__ void conv_rd_kernel(const float* __restrict__ src,
                               __nv_bfloat16* __restrict__ hi,
                               __nv_bfloat16* __restrict__ lo) {
    size_t i = (size_t)blockIdx.x * 256 + threadIdx.x;
    int d = (int)(i & 255);
    int v = (int)(i >> 8);
    float x = src[(size_t)d * VOCAB + v];
    split2(x, hi[i], lo[i]);
}

// ---------------- LayerNorm kernels -----------------------------------------
__global__ void embed_ln_kernel(const int* __restrict__ idx,
                                const float* __restrict__ wte,
                                float* __restrict__ out,
                                __nv_bfloat16* __restrict__ ohi,
                                __nv_bfloat16* __restrict__ olo) {
    __shared__ float sh[8];
    int row = blockIdx.x;
    int d = threadIdx.x;
    float x = wte[idx[row] * DD + d];
    int wid = d >> 5, lane = d & 31;
    float s = warp_sum(x);
    if (lane == 0) sh[wid] = s;
    __syncthreads();
    float tot = 0.f;
#pragma unroll
    for (int i = 0; i < 8; i++) tot += sh[i];
    float mu = tot * (1.f / 256.f);
    __syncthreads();
    float dx = x - mu;
    s = warp_sum(dx * dx);
    if (lane == 0) sh[wid] = s;
    __syncthreads();
    tot = 0.f;
#pragma unroll
    for (int i = 0; i < 8; i++) tot += sh[i];
    float r = dx * rsqrtf(tot * (1.f / 256.f) + EPS);
    out[row * DD + d] = r;
    split2(r, ohi[row * DD + d], olo[row * DD + d]);
}

__global__ void ln_split_kernel(const float* __restrict__ in,
                                __nv_bfloat16* __restrict__ ohi,
                                __nv_bfloat16* __restrict__ olo) {
    __shared__ float sh[8];
    int row = blockIdx.x;
    int d = threadIdx.x;
    float x = in[row * DD + d];
    int wid = d >> 5, lane = d & 31;
    float s = warp_sum(x);
    if (lane == 0) sh[wid] = s;
    __syncthreads();
    float tot = 0.f;
#pragma unroll
    for (int i = 0; i < 8; i++) tot += sh[i];
    float mu = tot * (1.f / 256.f);
    __syncthreads();
    float dx = x - mu;
    s = warp_sum(dx * dx);
    if (lane == 0) sh[wid] = s;
    __syncthreads();
    tot = 0.f;
#pragma unroll
    for (int i = 0; i < 8; i++) tot += sh[i];
    float r = dx * rsqrtf(tot * (1.f / 256.f) + EPS);
    split2(r, ohi[row * DD + d], olo[row * DD + d]);
}

__global__ void ln_add_kernel(const float* __restrict__ in,
                              float* __restrict__ v,
                              __nv_bfloat16* __restrict__ vhi,
                              __nv_bfloat16* __restrict__ vlo) {
    __shared__ float sh[8];
    int row = blockIdx.x;
    int d = threadIdx.x;
    float x = in[row * DD + d];
    int wid = d >> 5, lane = d & 31;
    float s = warp_sum(x);
    if (lane == 0) sh[wid] = s;
    __syncthreads();
    float tot = 0.f;
#pragma unroll
    for (int i = 0; i < 8; i++) tot += sh[i];
    float mu = tot * (1.f / 256.f);
    __syncthreads();
    float dx = x - mu;
    s = warp_sum(dx * dx);
    if (lane == 0) sh[wid] = s;
    __syncthreads();
    tot = 0.f;
#pragma unroll
    for (int i = 0; i < 8; i++) tot += sh[i];
    float nv = v[row * DD + d] + dx * rsqrtf(tot * (1.f / 256.f) + EPS);
    v[row * DD + d] = nv;
    split2(nv, vhi[row * DD + d], vlo[row * DD + d]);
}

// ---------------- RoPE: R = rope(v), fp32 + bf16 split ----------------------
__global__ void rope_split_kernel(const float* __restrict__ v,
                                  float* __restrict__ R,
                                  __nv_bfloat16* __restrict__ Rhi,
                                  __nv_bfloat16* __restrict__ Rlo) {
    int row = blockIdx.x;
    int d = threadIdx.x;
    int t = row & (TT - 1);
    float x = v[row * DD + d];
    float xr = (d < 128) ? -v[row * DD + d + 128] : v[row * DD + d - 128];
    int j = d & 127;
    float inv = expf(-(float)j * (2.f / 256.f) * 9.210340371976184f);
    float ang = (float)t * inv;
    const float TWO_PI_HI = 6.28318548202514648f;
    const float TWO_PI_LO = -1.74845553e-7f;
    float k = rintf(ang * 0.15915494309189535f);
    float r = fmaf(-k, TWO_PI_HI, ang);
    r = fmaf(-k, TWO_PI_LO, r);
    float sn = sinf(r), cs = cosf(r);
    float val = x * cs + xr * sn;
    R[row * DD + d] = val;
    split2(val, Rhi[row * DD + d], Rlo[row * DD + d]);
}

// ---------------- transpose + split: [b][t][256] -> hi/lo [b][256][2048] ----
__global__ void split_T_kernel(const float* __restrict__ in,
                               __nv_bfloat16* __restrict__ hi,
                               __nv_bfloat16* __restrict__ lo) {
    __shared__ float tile[32][33];
    int b = blockIdx.z;
    int t0 = blockIdx.x * 32;
    int d0 = blockIdx.y * 32;
    int tx = threadIdx.x & 31, ty = threadIdx.x >> 5;   // 256 threads: ty 0..7
#pragma unroll
    for (int i = 0; i < 4; i++) {
        int t = ty + i * 8;
        tile[t][tx] = in[((size_t)(b * TT + t0 + t)) * DD + d0 + tx];
    }
    __syncthreads();
#pragma unroll
    for (int i = 0; i < 4; i++) {
        int d = ty + i * 8;
        float x = tile[tx][d];
        size_t o = ((size_t)(b * DD + d0 + d)) * TT + t0 + tx;
        split2(x, hi[o], lo[o]);
    }
}

// ---------------- kv_outer: H[b][i] = V_i^T K_i (256x256, k=64) -------------
// A = VT[b][e][s] (rows e), B = RT[b][d][s] (rows d), both k-major over s.
#define KVO_SMEM 110592
__global__ void __launch_bounds__(512, 1)
kv_outer_kernel(const __nv_bfloat16* __restrict__ VThi,
                const __nv_bfloat16* __restrict__ VTlo,
                const __nv_bfloat16* __restrict__ RThi,
                const __nv_bfloat16* __restrict__ RTlo,
                float* __restrict__ H) {
    char* smc = dynsm;
    uint32_t sb = smem_u32(smc);
    int i = blockIdx.x, b = blockIdx.y, e0 = blockIdx.z * 128;
    int s0 = i * 64;
    int tid = threadIdx.x;
    int wid = tid >> 5, lane = tid & 31;
    int wm = wid & 3, wn = wid >> 2;

    // load VT tile (128 rows e) and RT tile (256 rows d), 64 s cols, hi/lo
    for (int l = tid; l < 1024; l += 512) {
        int r = l >> 3, c = l & 7;
        size_t g = ((size_t)(b * DD + e0 + r)) * TT + s0 + c * 8;
        uint32_t so = (uint32_t)(r * 144 + c * 16);
        *(uint4*)(smc + so) = *(const uint4*)(VThi + g);
        *(uint4*)(smc + 18432 + so) = *(const uint4*)(VTlo + g);
    }
    for (int l = tid; l < 2048; l += 512) {
        int r = l >> 3, c = l & 7;
        size_t g = ((size_t)(b * DD + r)) * TT + s0 + c * 8;
        uint32_t so = (uint32_t)(36864 + r * 144 + c * 16);
        *(uint4*)(smc + so) = *(const uint4*)(RThi + g);
        *(uint4*)(smc + 36864 + so) = *(const uint4*)(RTlo + g);
    }
    __syncthreads();

    uint32_t a_row_l = (uint32_t)(lane & 15);
    uint32_t a_col_l = (uint32_t)((lane >> 4) << 3);
    uint32_t b_row_l = (uint32_t)(((lane & 16) >> 1) + (lane & 7));
    uint32_t b_col_l = (uint32_t)(lane & 8);

    float acc[2][8][4] = {};
#pragma unroll
    for (int ks = 0; ks < 4; ks++) {
        uint32_t ah[2][4], al[2][4];
#pragma unroll
        for (int mi = 0; mi < 2; mi++) {
            uint32_t ad = sb + (uint32_t)(wm * 32 + mi * 16 + a_row_l) * 144
                        + (uint32_t)(ks * 16 + a_col_l) * 2;
            LDSM_X4(ah[mi][0], ah[mi][1], ah[mi][2], ah[mi][3], ad);
            LDSM_X4(al[mi][0], al[mi][1], al[mi][2], al[mi][3], ad + 18432);
        }
        uint32_t bh[8][2], bl[8][2];
#pragma unroll
        for (int p = 0; p < 4; p++) {
            uint32_t bd = sb + 36864 + (uint32_t)(wn * 64 + p * 16 + b_row_l) * 144
                        + (uint32_t)(ks * 16 + b_col_l) * 2;
            uint32_t q0, q1, q2, q3;
            LDSM_X4(q0, q1, q2, q3, bd);
            bh[2 * p][0] = q0; bh[2 * p][1] = q1;
            bh[2 * p + 1][0] = q2; bh[2 * p + 1][1] = q3;
            LDSM_X4(q0, q1, q2, q3, bd + 36864);
            bl[2 * p][0] = q0; bl[2 * p][1] = q1;
            bl[2 * p + 1][0] = q2; bl[2 * p + 1][1] = q3;
        }
#pragma unroll
        for (int mi = 0; mi < 2; mi++)
#pragma unroll
            for (int nt = 0; nt < 8; nt++)
                MMA_BF16(acc[mi][nt], ah[mi], bh[nt]);
#pragma unroll
        for (int mi = 0; mi < 2; mi++)
#pragma unroll
            for (int nt = 0; nt < 8; nt++)
                MMA_BF16(acc[mi][nt], ah[mi], bl[nt]);
#pragma unroll
        for (int mi = 0; mi < 2; mi++)
#pragma unroll
            for (int nt = 0; nt < 8; nt++)
                MMA_BF16(acc[mi][nt], al[mi], bh[nt]);
    }

    int tr = lane >> 2, tc = (lane & 3) * 2;
    size_t base = ((size_t)(b * 32 + i)) * 65536;
#pragma unroll
    for (int mi = 0; mi < 2; mi++) {
        int e = e0 + wm * 32 + mi * 16 + tr;
#pragma unroll
        for (int nt = 0; nt < 8; nt++) {
            int d = wn * 64 + nt * 8 + tc;
            *(float2*)&H[base + (size_t)e * 256 + d] =
                make_float2(acc[mi][nt][0], acc[mi][nt][1]);
            *(float2*)&H[base + (size_t)(e + 8) * 256 + d] =
                make_float2(acc[mi][nt][2], acc[mi][nt][3]);
        }
    }
}

// ---------------- exclusive prefix over chunks + bf16 split -----------------
__global__ void prefix_split_kernel(const float* __restrict__ H,
                                    __nv_bfloat16* __restrict__ Mhi,
                                    __nv_bfloat16* __restrict__ Mlo) {
    int b = blockIdx.y;
    int j = blockIdx.x * 256 + threadIdx.x;   // 0..65535
    size_t base = (size_t)b * 32 * 65536 + j;
    float acc = 0.f;
#pragma unroll 4
    for (int i = 0; i < 32; i++) {
        size_t off = base + (size_t)i * 65536;
        __nv_bfloat16 h, l;
        split2(acc, h, l);
        Mhi[off] = h;
        Mlo[off] = l;
        acc += H[off];
    }
}

// ---------------- attn_out: O_i = Q_i M_i + tril(Q_i K_i^T) V_i -------------
#define AO_Q   0
#define AO_QLO 33792
#define AO_B   67584
#define AO_BLO 104448
#define AO_S   141312
#define AO_SLO 150528
#define AO_SMEM 159744
__global__ void __launch_bounds__(256, 1)
attn_out_kernel(const __nv_bfloat16* __restrict__ Rhi,
                const __nv_bfloat16* __restrict__ Rlo,
                const __nv_bfloat16* __restrict__ VThi,
                const __nv_bfloat16* __restrict__ VTlo,
                const __nv_bfloat16* __restrict__ Mhi,
                const __nv_bfloat16* __restrict__ Mlo,
                float* __restrict__ Aout) {
    char* smc = dynsm;
    uint32_t sb = smem_u32(smc);
    int i = blockIdx.x, b = blockIdx.y;
    int q0 = i * 64;
    int tid = threadIdx.x;
    int wid = tid >> 5, lane = tid & 31;

    // load Q tile (64 rows x 256 d, hi/lo, row stride 528B)
    for (int l = tid; l < 2048; l += 256) {
        int r = l >> 5, c = l & 31;
        size_t g = ((size_t)(b * TT + q0 + r)) * DD + c * 8;
        uint32_t so = (uint32_t)(r * 528 + c * 16);
        *(uint4*)(smc + AO_Q + so) = *(const uint4*)(Rhi + g);
        *(uint4*)(smc + AO_QLO + so) = *(const uint4*)(Rlo + g);
    }
    // load VT tile into B buffer (256 rows e x 64 s, hi/lo, stride 144B)
    for (int l = tid; l < 2048; l += 256) {
        int r = l >> 3, c = l & 7;
        size_t g = ((size_t)(b * DD + r)) * TT + q0 + c * 8;
        uint32_t so = (uint32_t)(r * 144 + c * 16);
        *(uint4*)(smc + AO_B + so) = *(const uint4*)(VThi + g);
        *(uint4*)(smc + AO_BLO + so) = *(const uint4*)(VTlo + g);
    }
    __syncthreads();

    uint32_t a_row_l = (uint32_t)(lane & 15);
    uint32_t a_col_l = (uint32_t)((lane >> 4) << 3);
    uint32_t b_row_l = (uint32_t)(((lane & 16) >> 1) + (lane & 7));
    uint32_t b_col_l = (uint32_t)(lane & 8);
    int tr = lane >> 2, tc = (lane & 3) * 2;

    // ---- part 1: S = tril(Q K^T), K=256, warps: wt(2 t-halves) x ws(4 s-quarters)
    int wt = wid & 1, ws = wid >> 1;
    {
        float sacc[2][2][4] = {};
#pragma unroll
        for (int ks = 0; ks < 16; ks++) {
            uint32_t ah[2][4], al[2][4];
#pragma unroll
            for (int mi = 0; mi < 2; mi++) {
                uint32_t ad = sb + AO_Q + (uint32_t)(wt * 32 + mi * 16 + a_row_l) * 528
                            + (uint32_t)(ks * 16 + a_col_l) * 2;
                LDSM_X4(ah[mi][0], ah[mi][1], ah[mi][2], ah[mi][3], ad);
                LDSM_X4(al[mi][0], al[mi][1], al[mi][2], al[mi][3], ad + 33792);
            }
            uint32_t bh[2][2], bl[2][2];
            {
                uint32_t bd = sb + AO_Q + (uint32_t)(ws * 16 + b_row_l) * 528
                            + (uint32_t)(ks * 16 + b_col_l) * 2;
                uint32_t p0, p1, p2, p3;
                LDSM_X4(p0, p1, p2, p3, bd);
                bh[0][0] = p0; bh[0][1] = p1; bh[1][0] = p2; bh[1][1] = p3;
                LDSM_X4(p0, p1, p2, p3, bd + 33792);
                bl[0][0] = p0; bl[0][1] = p1; bl[1][0] = p2; bl[1][1] = p3;
            }
#pragma unroll
            for (int mi = 0; mi < 2; mi++)
#pragma unroll
                for (int ni = 0; ni < 2; ni++) {
                    MMA_BF16(sacc[mi][ni], ah[mi], bh[ni]);
                    MMA_BF16(sacc[mi][ni], ah[mi], bl[ni]);
                    MMA_BF16(sacc[mi][ni], al[mi], bh[ni]);
                }
        }
        // mask (strictly upper = 0), split, store to S smem
#pragma unroll
        for (int mi = 0; mi < 2; mi++)
#pragma unroll
            for (int ni = 0; ni < 2; ni++) {
                int t0l = wt * 32 + mi * 16 + tr;
                int sl = ws * 16 + ni * 8 + tc;
                float s0v = (sl > t0l) ? 0.f : sacc[mi][ni][0];
                float s1v = (sl + 1 > t0l) ? 0.f : sacc[mi][ni][1];
                float s2v = (sl > t0l + 8) ? 0.f : sacc[mi][ni][2];
                float s3v = (sl + 1 > t0l + 8) ? 0.f : sacc[mi][ni][3];
                __nv_bfloat16 h0, l0, h1, l1;
                split2(s0v, h0, l0); split2(s1v, h1, l1);
                *(__nv_bfloat162*)(smc + AO_S + t0l * 144 + sl * 2) = __halves2bfloat162(h0, h1);
                *(__nv_bfloat162*)(smc + AO_SLO + t0l * 144 + sl * 2) = __halves2bfloat162(l0, l1);
                split2(s2v, h0, l0); split2(s3v, h1, l1);
                *(__nv_bfloat162*)(smc + AO_S + (t0l + 8) * 144 + sl * 2) = __halves2bfloat162(h0, h1);
                *(__nv_bfloat162*)(smc + AO_SLO + (t0l + 8) * 144 + sl * 2) = __halves2bfloat162(l0, l1);
            }
    }
    __syncthreads();

    // ---- part 2: O += S @ V  (A = S [t][s], B = VT [e][s]); warps wt x we(4)
    int we = wid >> 1;
    float oacc[2][8][4] = {};
#pragma unroll
    for (int ks = 0; ks < 4; ks++) {
        uint32_t ah[2][4], al[2][4];
#pragma unroll
        for (int mi = 0; mi < 2; mi++) {
            uint32_t ad = sb + AO_S + (uint32_t)(wt * 32 + mi * 16 + a_row_l) * 144
                        + (uint32_t)(ks * 16 + a_col_l) * 2;
            LDSM_X4(ah[mi][0], ah[mi][1], ah[mi][2], ah[mi][3], ad);
            LDSM_X4(al[mi][0], al[mi][1], al[mi][2], al[mi][3], ad + 9216);
        }
        uint32_t bh[8][2], bl[8][2];
#pragma unroll
        for (int p = 0; p < 4; p++) {
            uint32_t bd = sb + AO_B + (uint32_t)(we * 64 + p * 16 + b_row_l) * 144
                        + (uint32_t)(ks * 16 + b_col_l) * 2;
            uint32_t p0, p1, p2, p3;
            LDSM_X4(p0, p1, p2, p3, bd);
            bh[2 * p][0] = p0; bh[2 * p][1] = p1;
            bh[2 * p + 1][0] = p2; bh[2 * p + 1][1] = p3;
            LDSM_X4(p0, p1, p2, p3, bd + 36864);
            bl[2 * p][0] = p0; bl[2 * p][1] = p1;
            bl[2 * p + 1][0] = p2; bl[2 * p + 1][1] = p3;
        }
#pragma unroll
        for (int mi = 0; mi < 2; mi++)
#pragma unroll
            for (int nt = 0; nt < 8; nt++) {
                MMA_BF16(oacc[mi][nt], ah[mi], bh[nt]);
                MMA_BF16(oacc[mi][nt], ah[mi], bl[nt]);
                MMA_BF16(oacc[mi][nt], al[mi], bh[nt]);
            }
    }
    __syncthreads();

    // ---- part 3: O += Q @ M  (B = M'[e][d] in 4 d-chunks)
    size_t mbase = ((size_t)(b * 32 + i)) * 65536;
    for (int dc = 0; dc < 4; dc++) {
        for (int l = tid; l < 2048; l += 256) {
            int r = l >> 3, c = l & 7;
            size_t g = mbase + (size_t)r * 256 + dc * 64 + c * 8;
            uint32_t so = (uint32_t)(r * 144 + c * 16);
            *(uint4*)(smc + AO_B + so) = *(const uint4*)(Mhi + g);
            *(uint4*)(smc + AO_BLO + so) = *(const uint4*)(Mlo + g);
        }
        __syncthreads();
#pragma unroll
        for (int ks = 0; ks < 4; ks++) {
            int ksg = dc * 4 + ks;
            uint32_t ah[2][4], al[2][4];
#pragma unroll
            for (int mi = 0; mi < 2; mi++) {
                uint32_t ad = sb + AO_Q + (uint32_t)(wt * 32 + mi * 16 + a_row_l) * 528
                            + (uint32_t)(ksg * 16 + a_col_l) * 2;
                LDSM_X4(ah[mi][0], ah[mi][1], ah[mi][2], ah[mi][3], ad);
                LDSM_X4(al[mi][0], al[mi][1], al[mi][2], al[mi][3], ad + 33792);
            }
            uint32_t bh[8][2], bl[8][2];
#pragma unroll
            for (int p = 0; p < 4; p++) {
                uint32_t bd = sb + AO_B + (uint32_t)(we * 64 + p * 16 + b_row_l) * 144
                            + (uint32_t)(ks * 16 + b_col_l) * 2;
                uint32_t p0, p1, p2, p3;
                LDSM_X4(p0, p1, p2, p3, bd);
                bh[2 * p][0] = p0; bh[2 * p][1] = p1;
                bh[2 * p + 1][0] = p2; bh[2 * p + 1][1] = p3;
                LDSM_X4(p0, p1, p2, p3, bd + 36864);
                bl[2 * p][0] = p0; bl[2 * p][1] = p1;
                bl[2 * p + 1][0] = p2; bl[2 * p + 1][1] = p3;
            }
#pragma unroll
            for (int mi = 0; mi < 2; mi++)
#pragma unroll
                for (int nt = 0; nt < 8; nt++) {
                    MMA_BF16(oacc[mi][nt], ah[mi], bh[nt]);
                    MMA_BF16(oacc[mi][nt], ah[mi], bl[nt]);
                    MMA_BF16(oacc[mi][nt], al[mi], bh[nt]);
                }
        }
        __syncthreads();
    }

    // write O
#pragma unroll
    for (int mi = 0; mi < 2; mi++) {
        int row = q0 + wt * 32 + mi * 16 + tr;
#pragma unroll
        for (int nt = 0; nt < 8; nt++) {
            int col = we * 64 + nt * 8 + tc;
            *(float2*)&Aout[((size_t)(b * TT + row)) * DD + col] =
                make_float2(oacc[mi][nt][0], oacc[mi][nt][1]);
            *(float2*)&Aout[((size_t)(b * TT + row + 8)) * DD + col] =
                make_float2(oacc[mi][nt][2], oacc[mi][nt][3]);
        }
    }
}

// ---------------- HMMA GEMM with cp.async double buffering ------------------
#define TILE_B 18432                       // 128 rows * 144 bytes
#define STAGE_B (4 * TILE_B)               // 73728
#define TCG_SMEM (2 * STAGE_B)             // 147456
__global__ void __launch_bounds__(256, 1)
tc_gemm(const __nv_bfloat16* __restrict__ Ahi, const __nv_bfloat16* __restrict__ Alo,
        const __nv_bfloat16* __restrict__ Bhi, const __nv_bfloat16* __restrict__ Blo,
        int K, int mode,
        float* __restrict__ C, int ldc,
        const float* __restrict__ gate,
        __nv_bfloat16* __restrict__ Ohi, __nv_bfloat16* __restrict__ Olo) {
    char* smc = dynsm;
    uint32_t sb = smem_u32(smc);

    int tid = threadIdx.x;
    int wid = tid >> 5;
    int lane = tid & 31;
    int warp_m = wid & 3;
    int warp_n = wid >> 2;

    int m0 = blockIdx.y * 128;
    int n0 = blockIdx.x * 128;

    float acc[2][8][4] = {};

    uint32_t a_row_l = (uint32_t)(lane & 15);
    uint32_t a_col_l = (uint32_t)((lane >> 4) << 3);
    uint32_t b_row_l = (uint32_t)(((lane & 16) >> 1) + (lane & 7));
    uint32_t b_col_l = (uint32_t)(lane & 8);

    // per-thread load coordinates (4 uint4 rows per tile)
    int lr[4], lcc[4];
#pragma unroll
    for (int q = 0; q < 4; q++) {
        int l = tid + q * 256;
        lr[q] = l >> 3;
        lcc[q] = l & 7;
    }

    int nchunks = K >> 6;

    // stage issue helper
    auto issue = [&](int st, int kc) {
        uint32_t sbase = sb + (uint32_t)st * STAGE_B;
#pragma unroll
        for (int q = 0; q < 4; q++) {
            int r = lr[q], c = lcc[q];
            uint32_t so = sbase + (uint32_t)(r * 144 + c * 16);
            size_t ga = (size_t)(m0 + r) * K + kc + c * 8;
            size_t gb = (size_t)(n0 + r) * K + kc + c * 8;
            CP_ASYNC16(so + 0 * TILE_B, (const void*)(Ahi + ga));
            CP_ASYNC16(so + 1 * TILE_B, (const void*)(Alo + ga));
            CP_ASYNC16(so + 2 * TILE_B, (const void*)(Bhi + gb));
            CP_ASYNC16(so + 3 * TILE_B, (const void*)(Blo + gb));
        }
    };

    issue(0, 0);
    CP_COMMIT();

    for (int ch = 0; ch < nchunks; ch++) {
        if (ch + 1 < nchunks) {
            issue((ch + 1) & 1, (ch + 1) << 6);
            CP_COMMIT();
            CP_WAIT(1);
        } else {
            CP_WAIT(0);
        }
        __syncthreads();

        uint32_t sA = sb + (uint32_t)(ch & 1) * STAGE_B;
        uint32_t sB = sA + 2 * TILE_B;
#pragma unroll
        for (int ks = 0; ks < 4; ks++) {
            uint32_t ah[2][4], al[2][4];
#pragma unroll
            for (int mt = 0; mt < 2; mt++) {
                uint32_t ad = sA + (uint32_t)(warp_m * 32 + mt * 16 + a_row_l) * 144
                            + (uint32_t)(ks * 16 + a_col_l) * 2;
                LDSM_X4(ah[mt][0], ah[mt][1], ah[mt][2], ah[mt][3], ad);
                LDSM_X4(al[mt][0], al[mt][1], al[mt][2], al[mt][3], ad + TILE_B);
            }
            uint32_t bh[8][2], bl[8][2];
#pragma unroll
            for (int p = 0; p < 4; p++) {
                uint32_t bd = sB + (uint32_t)(warp_n * 64 + p * 16 + b_row_l) * 144
                            + (uint32_t)(ks * 16 + b_col_l) * 2;
                uint32_t q0, q1, q2, q3;
                LDSM_X4(q0, q1, q2, q3, bd);
                bh[2 * p][0] = q0; bh[2 * p][1] = q1;
                bh[2 * p + 1][0] = q2; bh[2 * p + 1][1] = q3;
                LDSM_X4(q0, q1, q2, q3, bd + TILE_B);
                bl[2 * p][0] = q0; bl[2 * p][1] = q1;
                bl[2 * p + 1][0] = q2; bl[2 * p + 1][1] = q3;
            }
#pragma unroll
            for (int mt = 0; mt < 2; mt++)
#pragma unroll
                for (int nt = 0; nt < 8; nt++)
                    MMA_BF16(acc[mt][nt], ah[mt], bh[nt]);
#pragma unroll
            for (int mt = 0; mt < 2; mt++)
#pragma unroll
                for (int nt = 0; nt < 8; nt++)
                    MMA_BF16(acc[mt][nt], ah[mt], bl[nt]);
#pragma unroll
            for (int mt = 0; mt < 2; mt++)
#pragma unroll
                for (int nt = 0; nt < 8; nt++)
                    MMA_BF16(acc[mt][nt], al[mt], bh[nt]);
        }
        __syncthreads();
    }

    int tr = lane >> 2;
    int tc = (lane & 3) * 2;
    if (mode == 0) {
#pragma unroll
        for (int mt = 0; mt < 2; mt++) {
            int row = m0 + warp_m * 32 + mt * 16 + tr;
#pragma unroll
            for (int nt = 0; nt < 8; nt++) {
                int col = n0 + warp_n * 64 + nt * 8 + tc;
                *(float2*)&C[(size_t)row * ldc + col] =
                    make_float2(acc[mt][nt][0], acc[mt][nt][1]);
                *(float2*)&C[(size_t)(row + 8) * ldc + col] =
                    make_float2(acc[mt][nt][2], acc[mt][nt][3]);
            }
        }
    } else {
#pragma unroll
        for (int mt = 0; mt < 2; mt++) {
            int row = m0 + warp_m * 32 + mt * 16 + tr;
#pragma unroll
            for (int nt = 0; nt < 8; nt++) {
                int col = n0 + warp_n * 64 + nt * 8 + tc;
                size_t i0 = (size_t)row * NN + col;
                size_t i1 = (size_t)(row + 8) * NN + col;
                float2 gt0 = *(const float2*)&gate[i0];
                float2 gt1 = *(const float2*)&gate[i1];
                float g0 = fmaxf(acc[mt][nt][0], 0.f) * fmaxf(gt0.x, 0.f);
                float g1 = fmaxf(acc[mt][nt][1], 0.f) * fmaxf(gt0.y, 0.f);
                float g2 = fmaxf(acc[mt][nt][2], 0.f) * fmaxf(gt1.x, 0.f);
                float g3 = fmaxf(acc[mt][nt][3], 0.f) * fmaxf(gt1.y, 0.f);
                __nv_bfloat16 h0, l0, h1, l1;
                split2(g0, h0, l0); split2(g1, h1, l1);
                *(__nv_bfloat162*)(Ohi + i0) = __halves2bfloat162(h0, h1);
                *(__nv_bfloat162*)(Olo + i0) = __halves2bfloat162(l0, l1);
                split2(g2, h0, l0); split2(g3, h1, l1);
                *(__nv_bfloat162*)(Ohi + i1) = __halves2bfloat162(h0, h1);
                *(__nv_bfloat162*)(Olo + i1) = __halves2bfloat162(l0, l1);
            }
        }
    }
}

// ---------------- launch -----------------------------------------------------
extern "C" void kernel_launch(void* const* d_in, const int* in_sizes, int n_in,
                              void* d_out, int out_size) {
    const int* idx = (const int*)d_in[0];
    const float* wte = (const float*)d_in[1];
    const float* encoder = (const float*)d_in[2];
    const float* dec_x = (const float*)d_in[3];
    const float* dec_y = (const float*)d_in[4];
    const float* readout = (const float*)d_in[5];
    float* out = (float*)d_out;

    float *pv, *pR, *pa, *pu, *pX, *pH;
    __nv_bfloat16 *pvhi, *pvlo, *pRhi, *pRlo, *palnhi, *palnlo;
    __nv_bfloat16 *pwxhi, *pwxlo, *pwyhi, *pwylo, *penchi, *penclo, *prdhi, *prdlo;
    __nv_bfloat16 *pYhi, *pYlo, *pRThi, *pRTlo, *pVThi, *pVTlo, *pMhi, *pMlo;
    cudaGetSymbolAddress((void**)&pv, g_v);
    cudaGetSymbolAddress((void**)&pR, g_R);
    cudaGetSymbolAddress((void**)&pa, g_a);
    cudaGetSymbolAddress((void**)&pu, g_u);
    cudaGetSymbolAddress((void**)&pX, g_X);
    cudaGetSymbolAddress((void**)&pH, g_H);
    cudaGetSymbolAddress((void**)&pvhi, g_vhi);
    cudaGetSymbolAddress((void**)&pvlo, g_vlo);
    cudaGetSymbolAddress((void**)&pRhi, g_Rhi);
    cudaGetSymbolAddress((void**)&pRlo, g_Rlo);
    cudaGetSymbolAddress((void**)&palnhi, g_alnhi);
    cudaGetSymbolAddress((void**)&palnlo, g_alnlo);
    cudaGetSymbolAddress((void**)&pwxhi, g_wxhi);
    cudaGetSymbolAddress((void**)&pwxlo, g_wxlo);
    cudaGetSymbolAddress((void**)&pwyhi, g_wyhi);
    cudaGetSymbolAddress((void**)&pwylo, g_wylo);
    cudaGetSymbolAddress((void**)&penchi, g_enchi);
    cudaGetSymbolAddress((void**)&penclo, g_enclo);
    cudaGetSymbolAddress((void**)&prdhi, g_rdhi);
    cudaGetSymbolAddress((void**)&prdlo, g_rdlo);
    cudaGetSymbolAddress((void**)&pYhi, g_Yhi);
    cudaGetSymbolAddress((void**)&pYlo, g_Ylo);
    cudaGetSymbolAddress((void**)&pRThi, g_RThi);
    cudaGetSymbolAddress((void**)&pRTlo, g_RTlo);
    cudaGetSymbolAddress((void**)&pVThi, g_VThi);
    cudaGetSymbolAddress((void**)&pVTlo, g_VTlo);
    cudaGetSymbolAddress((void**)&pMhi, g_Mhi);
    cudaGetSymbolAddress((void**)&pMlo, g_Mlo);

    cudaFuncSetAttribute(tc_gemm,
                         cudaFuncAttributeMaxDynamicSharedMemorySize, TCG_SMEM);
    cudaFuncSetAttribute(kv_outer_kernel,
                         cudaFuncAttributeMaxDynamicSharedMemorySize, KVO_SMEM);
    cudaFuncSetAttribute(attn_out_kernel,
                         cudaFuncAttributeMaxDynamicSharedMemorySize, AO_SMEM);

    // one-time per-launch weight conversion (transpose + bf16 split)
    conv_dec_kernel<<<(NN * DD) / 256, 256>>>(dec_x, pwxhi, pwxlo);
    conv_dec_kernel<<<(NN * DD) / 256, 256>>>(dec_y, pwyhi, pwylo);
    conv_enc_kernel<<<(DD * NN) / 256, 256>>>(encoder, penchi, penclo);
    conv_rd_kernel<<<(VOCAB * DD) / 256, 256>>>(readout, prdhi, prdlo);

    embed_ln_kernel<<<BT, 256>>>(idx, wte, pv, pvhi, pvlo);

    for (int layer = 0; layer < LL; layer++) {
        // X = v @ Wx^T (only depends on v) — first so ncu capture lands here
        tc_gemm<<<dim3(NN / 128, BT / 128), 256, TCG_SMEM>>>(
            pvhi, pvlo, pwxhi, pwxlo, DD, 0, pX, NN, nullptr, nullptr, nullptr);

        // attention (chunked linear form)
        rope_split_kernel<<<BT, 256>>>(pv, pR, pRhi, pRlo);
        split_T_kernel<<<dim3(TT / 32, DD / 32, BB), 256>>>(pR, pRThi, pRTlo);
        split_T_kernel<<<dim3(TT / 32, DD / 32, BB), 256>>>(pv, pVThi, pVTlo);
        kv_outer_kernel<<<dim3(32, BB, 2), 512, KVO_SMEM>>>(pVThi, pVTlo,
                                                            pRThi, pRTlo, pH);
        prefix_split_kernel<<<dim3(256, BB), 256>>>(pH, pMhi, pMlo);
        attn_out_kernel<<<dim3(32, BB), 256, AO_SMEM>>>(pRhi, pRlo, pVThi, pVTlo,
                                                        pMhi, pMlo, pa);
        ln_split_kernel<<<BT, 256>>>(pa, palnhi, palnlo);

        // Y = relu(aln @ Wy^T) * relu(X), split to bf16
        tc_gemm<<<dim3(NN / 128, BT / 128), 256, TCG_SMEM>>>(
            palnhi, palnlo, pwyhi, pwylo, DD, 2, nullptr, 0, pX, pYhi, pYlo);
        // u = Y @ encoder
        tc_gemm<<<dim3(DD / 128, BT / 128), 256, TCG_SMEM>>>(
            pYhi, pYlo, penchi, penclo, NN, 0, pu, DD, nullptr, nullptr, nullptr);
        ln_add_kernel<<<BT, 256>>>(pu, pv, pvhi, pvlo);
    }

    // logits = v @ readout
    tc_gemm<<<dim3(VOCAB / 128, BT / 128), 256, TCG_SMEM>>>(
        pvhi, pvlo, prdhi, prdlo, DD, 0, out, VOCAB, nullptr, nullptr, nullptr);
}

// round 6
// speedup vs baseline: 6.4630x; 1.0155x over previous
#include <cuda_runtime.h>
#include <cuda_bf16.h>
#include <math.h>
#include <stdint.h>

// Problem constants
#define BB 4
#define TT 2048
#define BT 8192      // B*T
#define DD 256
#define NN 8192
#define HH 4
#define MM 2048      // N/H
#define LL 6
#define VOCAB 256
#define EPS 1e-5f

// single dynamic-smem declaration shared by all kernels
extern __shared__ char dynsm[];

// ---------------- scratch buffers (device globals, no allocations) --------
__device__ float g_v[BT * DD];
__device__ float g_R[BT * DD];
__device__ float g_a[BT * DD];
__device__ float g_u[BT * DD];
__device__ __nv_bfloat16 g_vhi[BT * DD], g_vlo[BT * DD];
__device__ __nv_bfloat16 g_Rhi[BT * DD], g_Rlo[BT * DD];
__device__ __nv_bfloat16 g_alnhi[BT * DD], g_alnlo[BT * DD];
__device__ __nv_bfloat16 g_wxhi[NN * DD], g_wxlo[NN * DD];
__device__ __nv_bfloat16 g_wyhi[NN * DD], g_wylo[NN * DD];
__device__ __nv_bfloat16 g_enchi[DD * NN], g_enclo[DD * NN];
__device__ __nv_bfloat16 g_rdhi[VOCAB * DD], g_rdlo[VOCAB * DD];
__device__ __nv_bfloat16 g_Yhi[(size_t)BT * NN];             // 128 MB
__device__ __nv_bfloat16 g_Ylo[(size_t)BT * NN];             // 128 MB
// linear-attention scratch
__device__ __nv_bfloat16 g_RThi[BB * DD * TT], g_RTlo[BB * DD * TT];  // [b][d][t]
__device__ __nv_bfloat16 g_VThi[BB * DD * TT], g_VTlo[BB * DD * TT];  // [b][e][t]
__device__ float g_H[(size_t)BB * 32 * DD * DD];
__device__ __nv_bfloat16 g_Mhi[(size_t)BB * 32 * DD * DD];
__device__ __nv_bfloat16 g_Mlo[(size_t)BB * 32 * DD * DD];

// ---------------- PTX helpers ----------------------------------------------
__device__ __forceinline__ uint32_t smem_u32(const void* p) {
    uint32_t a;
    asm("{ .reg .u64 t; cvta.to.shared.u64 t, %1; cvt.u32.u64 %0, t; }"
        : "=r"(a) : "l"(p));
    return a;
}

#define LDSM_X4(r0, r1, r2, r3, addr) \
    asm volatile("ldmatrix.sync.aligned.m8n8.x4.shared.b16 {%0,%1,%2,%3}, [%4];" \
        : "=r"(r0), "=r"(r1), "=r"(r2), "=r"(r3) : "r"(addr))

#define MMA_BF16(d, a, b) \
    asm volatile( \
        "mma.sync.aligned.m16n8k16.row.col.f32.bf16.bf16.f32 " \
        "{%0,%1,%2,%3}, {%4,%5,%6,%7}, {%8,%9}, {%0,%1,%2,%3};" \
        : "+f"((d)[0]), "+f"((d)[1]), "+f"((d)[2]), "+f"((d)[3]) \
        : "r"((a)[0]), "r"((a)[1]), "r"((a)[2]), "r"((a)[3]), \
          "r"((b)[0]), "r"((b)[1]))

#define CP_ASYNC16(dst, src) \
    asm volatile("cp.async.cg.shared.global [%0], [%1], 16;" \
        :: "r"(dst), "l"(src) : "memory")
#define CP_COMMIT() asm volatile("cp.async.commit_group;" ::: "memory")
#define CP_WAIT(N)  asm volatile("cp.async.wait_group %0;" :: "n"(N) : "memory")

// ---------------- misc helpers ----------------------------------------------
__device__ __forceinline__ float warp_sum(float v) {
#pragma unroll
    for (int o = 16; o > 0; o >>= 1) v += __shfl_xor_sync(0xffffffffu, v, o);
    return v;
}
__device__ __forceinline__ void split2(float x, __nv_bfloat16& h, __nv_bfloat16& l) {
    __nv_bfloat16 hh = __float2bfloat16(x);
    h = hh;
    l = __float2bfloat16(x - __bfloat162float(hh));
}
__device__ __forceinline__ float rope_val(const float* rowbuf, int d, int t) {
    float x = rowbuf[d];
    float xr = (d < 128) ? -rowbuf[d + 128] : rowbuf[d - 128];
    int j = d & 127;
    float inv = expf(-(float)j * (2.f / 256.f) * 9.210340371976184f);
    float ang = (float)t * inv;
    const float TWO_PI_HI = 6.28318548202514648f;
    const float TWO_PI_LO = -1.74845553e-7f;
    float k = rintf(ang * 0.15915494309189535f);
    float r = fmaf(-k, TWO_PI_HI, ang);
    r = fmaf(-k, TWO_PI_LO, r);
    float sn = sinf(r), cs = cosf(r);
    return x * cs + xr * sn;
}

// ---------------- weight conversion (transpose + bf16 split) ----------------
__global__ void conv_dec_kernel(const float* __restrict__ src,
                                __nv_bfloat16* __restrict__ hi,
                                __nv_bfloat16* __restrict__ lo) {
    size_t i = (size_t)blockIdx.x * 256 + threadIdx.x;
    int d = (int)(i & 255);
    size_t n = i >> 8;
    int h = (int)(n >> 11);
    int m = (int)(n & 2047);
    float x = src[((size_t)h * DD + d) * MM + m];
    split2(x, hi[i], lo[i]);
}
__global__ void conv_enc_kernel(const float* __restrict__ src,
                                __nv_bfloat16* __restrict__ hi,
                                __nv_bfloat16* __restrict__ lo) {
    size_t i = (size_t)blockIdx.x * 256 + threadIdx.x;
    int n = (int)(i & 8191);
    int d = (int)(i >> 13);
    float x = src[(size_t)n * DD + d];
    split2(x, hi[i], lo[i]);
}
__global__ void conv_rd_kernel(const float* __restrict__ src,
                               __nv_bfloat16* __restrict__ hi,
                               __nv_bfloat16* __restrict__ lo) {
    size_t i = (size_t)blockIdx.x * 256 + threadIdx.x;
    int d = (int)(i & 255);
    int v = (int)(i >> 8);
    float x = src[(size_t)d * VOCAB + v];
    split2(x, hi[i], lo[i]);
}

// ---------------- embed + LN + RoPE ------------------------------------------
__global__ void embed_ln_rope_kernel(const int* __restrict__ idx,
                                     const float* __restrict__ wte,
                                     float* __restrict__ out,
                                     __nv_bfloat16* __restrict__ ohi,
                                     __nv_bfloat16* __restrict__ olo,
                                     float* __restrict__ R,
                                     __nv_bfloat16* __restrict__ Rhi,
                                     __nv_bfloat16* __restrict__ Rlo) {
    __shared__ float sh[8];
    __shared__ float rowbuf[256];
    int row = blockIdx.x;
    int d = threadIdx.x;
    float x = wte[idx[row] * DD + d];
    int wid = d >> 5, lane = d & 31;
    float s = warp_sum(x);
    if (lane == 0) sh[wid] = s;
    __syncthreads();
    float tot = 0.f;
#pragma unroll
    for (int i = 0; i < 8; i++) tot += sh[i];
    float mu = tot * (1.f / 256.f);
    __syncthreads();
    float dx = x - mu;
    s = warp_sum(dx * dx);
    if (lane == 0) sh[wid] = s;
    __syncthreads();
    tot = 0.f;
#pragma unroll
    for (int i = 0; i < 8; i++) tot += sh[i];
    float r = dx * rsqrtf(tot * (1.f / 256.f) + EPS);
    out[row * DD + d] = r;
    split2(r, ohi[row * DD + d], olo[row * DD + d]);
    rowbuf[d] = r;
    __syncthreads();
    float val = rope_val(rowbuf, d, row & (TT - 1));
    R[row * DD + d] = val;
    split2(val, Rhi[row * DD + d], Rlo[row * DD + d]);
}

// ---------------- LN (a -> aln hi/lo) ----------------------------------------
__global__ void ln_split_kernel(const float* __restrict__ in,
                                __nv_bfloat16* __restrict__ ohi,
                                __nv_bfloat16* __restrict__ olo) {
    __shared__ float sh[8];
    int row = blockIdx.x;
    int d = threadIdx.x;
    float x = in[row * DD + d];
    int wid = d >> 5, lane = d & 31;
    float s = warp_sum(x);
    if (lane == 0) sh[wid] = s;
    __syncthreads();
    float tot = 0.f;
#pragma unroll
    for (int i = 0; i < 8; i++) tot += sh[i];
    float mu = tot * (1.f / 256.f);
    __syncthreads();
    float dx = x - mu;
    s = warp_sum(dx * dx);
    if (lane == 0) sh[wid] = s;
    __syncthreads();
    tot = 0.f;
#pragma unroll
    for (int i = 0; i < 8; i++) tot += sh[i];
    float r = dx * rsqrtf(tot * (1.f / 256.f) + EPS);
    split2(r, ohi[row * DD + d], olo[row * DD + d]);
}

// ---------------- LN + residual add + RoPE for next layer --------------------
__global__ void ln_add_rope_kernel(const float* __restrict__ in,
                                   float* __restrict__ v,
                                   __nv_bfloat16* __restrict__ vhi,
                                   __nv_bfloat16* __restrict__ vlo,
                                   float* __restrict__ R,
                                   __nv_bfloat16* __restrict__ Rhi,
                                   __nv_bfloat16* __restrict__ Rlo) {
    __shared__ float sh[8];
    __shared__ float rowbuf[256];
    int row = blockIdx.x;
    int d = threadIdx.x;
    float x = in[row * DD + d];
    int wid = d >> 5, lane = d & 31;
    float s = warp_sum(x);
    if (lane == 0) sh[wid] = s;
    __syncthreads();
    float tot = 0.f;
#pragma unroll
    for (int i = 0; i < 8; i++) tot += sh[i];
    float mu = tot * (1.f / 256.f);
    __syncthreads();
    float dx = x - mu;
    s = warp_sum(dx * dx);
    if (lane == 0) sh[wid] = s;
    __syncthreads();
    tot = 0.f;
#pragma unroll
    for (int i = 0; i < 8; i++) tot += sh[i];
    float nv = v[row * DD + d] + dx * rsqrtf(tot * (1.f / 256.f) + EPS);
    v[row * DD + d] = nv;
    split2(nv, vhi[row * DD + d], vlo[row * DD + d]);
    rowbuf[d] = nv;
    __syncthreads();
    float val = rope_val(rowbuf, d, row & (TT - 1));
    R[row * DD + d] = val;
    split2(val, Rhi[row * DD + d], Rlo[row * DD + d]);
}

// ---------------- transpose + split: [b][t][256] -> hi/lo [b][256][2048] ----
__global__ void split_T_kernel(const float* __restrict__ in,
                               __nv_bfloat16* __restrict__ hi,
                               __nv_bfloat16* __restrict__ lo) {
    __shared__ float tile[32][33];
    int b = blockIdx.z;
    int t0 = blockIdx.x * 32;
    int d0 = blockIdx.y * 32;
    int tx = threadIdx.x & 31, ty = threadIdx.x >> 5;
#pragma unroll
    for (int i = 0; i < 4; i++) {
        int t = ty + i * 8;
        tile[t][tx] = in[((size_t)(b * TT + t0 + t)) * DD + d0 + tx];
    }
    __syncthreads();
#pragma unroll
    for (int i = 0; i < 4; i++) {
        int d = ty + i * 8;
        float x = tile[tx][d];
        size_t o = ((size_t)(b * DD + d0 + d)) * TT + t0 + tx;
        split2(x, hi[o], lo[o]);
    }
}

// ---------------- kv_outer: H[b][i] = V_i^T K_i (256x256, k=64) -------------
#define KVO_SMEM 110592
__global__ void __launch_bounds__(512, 1)
kv_outer_kernel(const __nv_bfloat16* __restrict__ VThi,
                const __nv_bfloat16* __restrict__ VTlo,
                const __nv_bfloat16* __restrict__ RThi,
                const __nv_bfloat16* __restrict__ RTlo,
                float* __restrict__ H) {
    char* smc = dynsm;
    uint32_t sb = smem_u32(smc);
    int i = blockIdx.x, b = blockIdx.y, e0 = blockIdx.z * 128;
    int s0 = i * 64;
    int tid = threadIdx.x;
    int wid = tid >> 5, lane = tid & 31;
    int wm = wid & 3, wn = wid >> 2;

    for (int l = tid; l < 1024; l += 512) {
        int r = l >> 3, c = l & 7;
        size_t g = ((size_t)(b * DD + e0 + r)) * TT + s0 + c * 8;
        uint32_t so = (uint32_t)(r * 144 + c * 16);
        *(uint4*)(smc + so) = *(const uint4*)(VThi + g);
        *(uint4*)(smc + 18432 + so) = *(const uint4*)(VTlo + g);
    }
    for (int l = tid; l < 2048; l += 512) {
        int r = l >> 3, c = l & 7;
        size_t g = ((size_t)(b * DD + r)) * TT + s0 + c * 8;
        uint32_t so = (uint32_t)(36864 + r * 144 + c * 16);
        *(uint4*)(smc + so) = *(const uint4*)(RThi + g);
        *(uint4*)(smc + 36864 + so) = *(const uint4*)(RTlo + g);
    }
    __syncthreads();

    uint32_t a_row_l = (uint32_t)(lane & 15);
    uint32_t a_col_l = (uint32_t)((lane >> 4) << 3);
    uint32_t b_row_l = (uint32_t)(((lane & 16) >> 1) + (lane & 7));
    uint32_t b_col_l = (uint32_t)(lane & 8);

    float acc[2][8][4] = {};
#pragma unroll
    for (int ks = 0; ks < 4; ks++) {
        uint32_t ah[2][4], al[2][4];
#pragma unroll
        for (int mi = 0; mi < 2; mi++) {
            uint32_t ad = sb + (uint32_t)(wm * 32 + mi * 16 + a_row_l) * 144
                        + (uint32_t)(ks * 16 + a_col_l) * 2;
            LDSM_X4(ah[mi][0], ah[mi][1], ah[mi][2], ah[mi][3], ad);
            LDSM_X4(al[mi][0], al[mi][1], al[mi][2], al[mi][3], ad + 18432);
        }
        uint32_t bh[8][2], bl[8][2];
#pragma unroll
        for (int p = 0; p < 4; p++) {
            uint32_t bd = sb + 36864 + (uint32_t)(wn * 64 + p * 16 + b_row_l) * 144
                        + (uint32_t)(ks * 16 + b_col_l) * 2;
            uint32_t q0, q1, q2, q3;
            LDSM_X4(q0, q1, q2, q3, bd);
            bh[2 * p][0] = q0; bh[2 * p][1] = q1;
            bh[2 * p + 1][0] = q2; bh[2 * p + 1][1] = q3;
            LDSM_X4(q0, q1, q2, q3, bd + 36864);
            bl[2 * p][0] = q0; bl[2 * p][1] = q1;
            bl[2 * p + 1][0] = q2; bl[2 * p + 1][1] = q3;
        }
#pragma unroll
        for (int mi = 0; mi < 2; mi++)
#pragma unroll
            for (int nt = 0; nt < 8; nt++)
                MMA_BF16(acc[mi][nt], ah[mi], bh[nt]);
#pragma unroll
        for (int mi = 0; mi < 2; mi++)
#pragma unroll
            for (int nt = 0; nt < 8; nt++)
                MMA_BF16(acc[mi][nt], ah[mi], bl[nt]);
#pragma unroll
        for (int mi = 0; mi < 2; mi++)
#pragma unroll
            for (int nt = 0; nt < 8; nt++)
                MMA_BF16(acc[mi][nt], al[mi], bh[nt]);
    }

    int tr = lane >> 2, tc = (lane & 3) * 2;
    size_t base = ((size_t)(b * 32 + i)) * 65536;
#pragma unroll
    for (int mi = 0; mi < 2; mi++) {
        int e = e0 + wm * 32 + mi * 16 + tr;
#pragma unroll
        for (int nt = 0; nt < 8; nt++) {
            int d = wn * 64 + nt * 8 + tc;
            *(float2*)&H[base + (size_t)e * 256 + d] =
                make_float2(acc[mi][nt][0], acc[mi][nt][1]);
            *(float2*)&H[base + (size_t)(e + 8) * 256 + d] =
                make_float2(acc[mi][nt][2], acc[mi][nt][3]);
        }
    }
}

// ---------------- exclusive prefix over chunks + bf16 split -----------------
__global__ void prefix_split_kernel(const float* __restrict__ H,
                                    __nv_bfloat16* __restrict__ Mhi,
                                    __nv_bfloat16* __restrict__ Mlo) {
    int b = blockIdx.y;
    int j = blockIdx.x * 256 + threadIdx.x;
    size_t base = (size_t)b * 32 * 65536 + j;
    float acc = 0.f;
#pragma unroll 4
    for (int i = 0; i < 32; i++) {
        size_t off = base + (size_t)i * 65536;
        __nv_bfloat16 h, l;
        split2(acc, h, l);
        Mhi[off] = h;
        Mlo[off] = l;
        acc += H[off];
    }
}

// ---------------- attn_out: O_i = Q_i M_i + tril(Q_i K_i^T) V_i -------------
#define AO_Q   0
#define AO_QLO 33792
#define AO_B   67584
#define AO_BLO 104448
#define AO_S   141312
#define AO_SLO 150528
#define AO_SMEM 159744
__global__ void __launch_bounds__(256, 1)
attn_out_kernel(const __nv_bfloat16* __restrict__ Rhi,
                const __nv_bfloat16* __restrict__ Rlo,
                const __nv_bfloat16* __restrict__ VThi,
                const __nv_bfloat16* __restrict__ VTlo,
                const __nv_bfloat16* __restrict__ Mhi,
                const __nv_bfloat16* __restrict__ Mlo,
                float* __restrict__ Aout) {
    char* smc = dynsm;
    uint32_t sb = smem_u32(smc);
    int i = blockIdx.x, b = blockIdx.y;
    int q0 = i * 64;
    int tid = threadIdx.x;
    int wid = tid >> 5, lane = tid & 31;

    for (int l = tid; l < 2048; l += 256) {
        int r = l >> 5, c = l & 31;
        size_t g = ((size_t)(b * TT + q0 + r)) * DD + c * 8;
        uint32_t so = (uint32_t)(r * 528 + c * 16);
        *(uint4*)(smc + AO_Q + so) = *(const uint4*)(Rhi + g);
        *(uint4*)(smc + AO_QLO + so) = *(const uint4*)(Rlo + g);
    }
    for (int l = tid; l < 2048; l += 256) {
        int r = l >> 3, c = l & 7;
        size_t g = ((size_t)(b * DD + r)) * TT + q0 + c * 8;
        uint32_t so = (uint32_t)(r * 144 + c * 16);
        *(uint4*)(smc + AO_B + so) = *(const uint4*)(VThi + g);
        *(uint4*)(smc + AO_BLO + so) = *(const uint4*)(VTlo + g);
    }
    __syncthreads();

    uint32_t a_row_l = (uint32_t)(lane & 15);
    uint32_t a_col_l = (uint32_t)((lane >> 4) << 3);
    uint32_t b_row_l = (uint32_t)(((lane & 16) >> 1) + (lane & 7));
    uint32_t b_col_l = (uint32_t)(lane & 8);
    int tr = lane >> 2, tc = (lane & 3) * 2;

    int wt = wid & 1, ws = wid >> 1;
    {
        float sacc[2][2][4] = {};
#pragma unroll
        for (int ks = 0; ks < 16; ks++) {
            uint32_t ah[2][4], al[2][4];
#pragma unroll
            for (int mi = 0; mi < 2; mi++) {
                uint32_t ad = sb + AO_Q + (uint32_t)(wt * 32 + mi * 16 + a_row_l) * 528
                            + (uint32_t)(ks * 16 + a_col_l) * 2;
                LDSM_X4(ah[mi][0], ah[mi][1], ah[mi][2], ah[mi][3], ad);
                LDSM_X4(al[mi][0], al[mi][1], al[mi][2], al[mi][3], ad + 33792);
            }
            uint32_t bh[2][2], bl[2][2];
            {
                uint32_t bd = sb + AO_Q + (uint32_t)(ws * 16 + b_row_l) * 528
                            + (uint32_t)(ks * 16 + b_col_l) * 2;
                uint32_t p0, p1, p2, p3;
                LDSM_X4(p0, p1, p2, p3, bd);
                bh[0][0] = p0; bh[0][1] = p1; bh[1][0] = p2; bh[1][1] = p3;
                LDSM_X4(p0, p1, p2, p3, bd + 33792);
                bl[0][0] = p0; bl[0][1] = p1; bl[1][0] = p2; bl[1][1] = p3;
            }
#pragma unroll
            for (int mi = 0; mi < 2; mi++)
#pragma unroll
                for (int ni = 0; ni < 2; ni++) {
                    MMA_BF16(sacc[mi][ni], ah[mi], bh[ni]);
                    MMA_BF16(sacc[mi][ni], ah[mi], bl[ni]);
                    MMA_BF16(sacc[mi][ni], al[mi], bh[ni]);
                }
        }
#pragma unroll
        for (int mi = 0; mi < 2; mi++)
#pragma unroll
            for (int ni = 0; ni < 2; ni++) {
                int t0l = wt * 32 + mi * 16 + tr;
                int sl = ws * 16 + ni * 8 + tc;
                float s0v = (sl > t0l) ? 0.f : sacc[mi][ni][0];
                float s1v = (sl + 1 > t0l) ? 0.f : sacc[mi][ni][1];
                float s2v = (sl > t0l + 8) ? 0.f : sacc[mi][ni][2];
                float s3v = (sl + 1 > t0l + 8) ? 0.f : sacc[mi][ni][3];
                __nv_bfloat16 h0, l0, h1, l1;
                split2(s0v, h0, l0); split2(s1v, h1, l1);
                *(__nv_bfloat162*)(smc + AO_S + t0l * 144 + sl * 2) = __halves2bfloat162(h0, h1);
                *(__nv_bfloat162*)(smc + AO_SLO + t0l * 144 + sl * 2) = __halves2bfloat162(l0, l1);
                split2(s2v, h0, l0); split2(s3v, h1, l1);
                *(__nv_bfloat162*)(smc + AO_S + (t0l + 8) * 144 + sl * 2) = __halves2bfloat162(h0, h1);
                *(__nv_bfloat162*)(smc + AO_SLO + (t0l + 8) * 144 + sl * 2) = __halves2bfloat162(l0, l1);
            }
    }
    __syncthreads();

    int we = wid >> 1;
    float oacc[2][8][4] = {};
#pragma unroll
    for (int ks = 0; ks < 4; ks++) {
        uint32_t ah[2][4], al[2][4];
#pragma unroll
        for (int mi = 0; mi < 2; mi++) {
            uint32_t ad = sb + AO_S + (uint32_t)(wt * 32 + mi * 16 + a_row_l) * 144
                        + (uint32_t)(ks * 16 + a_col_l) * 2;
            LDSM_X4(ah[mi][0], ah[mi][1], ah[mi][2], ah[mi][3], ad);
            LDSM_X4(al[mi][0], al[mi][1], al[mi][2], al[mi][3], ad + 9216);
        }
        uint32_t bh[8][2], bl[8][2];
#pragma unroll
        for (int p = 0; p < 4; p++) {
            uint32_t bd = sb + AO_B + (uint32_t)(we * 64 + p * 16 + b_row_l) * 144
                        + (uint32_t)(ks * 16 + b_col_l) * 2;
            uint32_t p0, p1, p2, p3;
            LDSM_X4(p0, p1, p2, p3, bd);
            bh[2 * p][0] = p0; bh[2 * p][1] = p1;
            bh[2 * p + 1][0] = p2; bh[2 * p + 1][1] = p3;
            LDSM_X4(p0, p1, p2, p3, bd + 36864);
            bl[2 * p][0] = p0; bl[2 * p][1] = p1;
            bl[2 * p + 1][0] = p2; bl[2 * p + 1][1] = p3;
        }
#pragma unroll
        for (int mi = 0; mi < 2; mi++)
#pragma unroll
            for (int nt = 0; nt < 8; nt++) {
                MMA_BF16(oacc[mi][nt], ah[mi], bh[nt]);
                MMA_BF16(oacc[mi][nt], ah[mi], bl[nt]);
                MMA_BF16(oacc[mi][nt], al[mi], bh[nt]);
            }
    }
    __syncthreads();

    size_t mbase = ((size_t)(b * 32 + i)) * 65536;
    for (int dc = 0; dc < 4; dc++) {
        for (int l = tid; l < 2048; l += 256) {
            int r = l >> 3, c = l & 7;
            size_t g = mbase + (size_t)r * 256 + dc * 64 + c * 8;
            uint32_t so = (uint32_t)(r * 144 + c * 16);
            *(uint4*)(smc + AO_B + so) = *(const uint4*)(Mhi + g);
            *(uint4*)(smc + AO_BLO + so) = *(const uint4*)(Mlo + g);
        }
        __syncthreads();
#pragma unroll
        for (int ks = 0; ks < 4; ks++) {
            int ksg = dc * 4 + ks;
            uint32_t ah[2][4], al[2][4];
#pragma unroll
            for (int mi = 0; mi < 2; mi++) {
                uint32_t ad = sb + AO_Q + (uint32_t)(wt * 32 + mi * 16 + a_row_l) * 528
                            + (uint32_t)(ksg * 16 + a_col_l) * 2;
                LDSM_X4(ah[mi][0], ah[mi][1], ah[mi][2], ah[mi][3], ad);
                LDSM_X4(al[mi][0], al[mi][1], al[mi][2], al[mi][3], ad + 33792);
            }
            uint32_t bh[8][2], bl[8][2];
#pragma unroll
            for (int p = 0; p < 4; p++) {
                uint32_t bd = sb + AO_B + (uint32_t)(we * 64 + p * 16 + b_row_l) * 144
                            + (uint32_t)(ks * 16 + b_col_l) * 2;
                uint32_t p0, p1, p2, p3;
                LDSM_X4(p0, p1, p2, p3, bd);
                bh[2 * p][0] = p0; bh[2 * p][1] = p1;
                bh[2 * p + 1][0] = p2; bh[2 * p + 1][1] = p3;
                LDSM_X4(p0, p1, p2, p3, bd + 36864);
                bl[2 * p][0] = p0; bl[2 * p][1] = p1;
                bl[2 * p + 1][0] = p2; bl[2 * p + 1][1] = p3;
            }
#pragma unroll
            for (int mi = 0; mi < 2; mi++)
#pragma unroll
                for (int nt = 0; nt < 8; nt++) {
                    MMA_BF16(oacc[mi][nt], ah[mi], bh[nt]);
                    MMA_BF16(oacc[mi][nt], ah[mi], bl[nt]);
                    MMA_BF16(oacc[mi][nt], al[mi], bh[nt]);
                }
        }
        __syncthreads();
    }

#pragma unroll
    for (int mi = 0; mi < 2; mi++) {
        int row = q0 + wt * 32 + mi * 16 + tr;
#pragma unroll
        for (int nt = 0; nt < 8; nt++) {
            int col = we * 64 + nt * 8 + tc;
            *(float2*)&Aout[((size_t)(b * TT + row)) * DD + col] =
                make_float2(oacc[mi][nt][0], oacc[mi][nt][1]);
            *(float2*)&Aout[((size_t)(b * TT + row + 8)) * DD + col] =
                make_float2(oacc[mi][nt][2], oacc[mi][nt][3]);
        }
    }
}

// ---------------- fused XY GEMM ----------------------------------------------
// accx = v @ Wx^T, accy = aln @ Wy^T (both 128x128 CTA tile, K=256, chunk 32),
// Y = relu(accy)*relu(accx) -> split bf16 hi/lo. 2-stage cp.async.
#define XT 10240                 // 128 rows * 80B (32 bf16 cols padded)
#define XSTG (8 * XT)            // 81920
#define XY_SMEM (2 * XSTG)       // 163840
__global__ void __launch_bounds__(256, 1)
xy_gemm(const __nv_bfloat16* __restrict__ vhi, const __nv_bfloat16* __restrict__ vlo,
        const __nv_bfloat16* __restrict__ alnhi, const __nv_bfloat16* __restrict__ alnlo,
        const __nv_bfloat16* __restrict__ wxhi, const __nv_bfloat16* __restrict__ wxlo,
        const __nv_bfloat16* __restrict__ wyhi, const __nv_bfloat16* __restrict__ wylo,
        __nv_bfloat16* __restrict__ Yhi, __nv_bfloat16* __restrict__ Ylo) {
    char* smc = dynsm;
    uint32_t sb = smem_u32(smc);

    int tid = threadIdx.x;
    int wid = tid >> 5;
    int lane = tid & 31;
    int warp_m = wid & 3;
    int warp_n = wid >> 2;

    int m0 = blockIdx.y * 128;
    int n0 = blockIdx.x * 128;

    float accx[2][8][4] = {};
    float accy[2][8][4] = {};

    uint32_t a_row_l = (uint32_t)(lane & 15);
    uint32_t a_col_l = (uint32_t)((lane >> 4) << 3);
    uint32_t b_row_l = (uint32_t)(((lane & 16) >> 1) + (lane & 7));
    uint32_t b_col_l = (uint32_t)(lane & 8);

    int rr = tid >> 2;           // 0..63 row within half-tile
    int cc = tid & 3;            // 16B col

    // issue one stage: 8 tiles x (128 rows x 2 halves)
#define XY_ISSUE(st, kc) do {                                                  \
    uint32_t sbase = sb + (uint32_t)(st) * XSTG;                               \
    _Pragma("unroll")                                                          \
    for (int q = 0; q < 16; q++) {                                             \
        int tile = q >> 1;                                                     \
        int r = ((q & 1) << 6) + rr;                                           \
        const __nv_bfloat16* mat;                                              \
        int rb;                                                                \
        switch (tile) {                                                        \
            case 0: mat = vhi;   rb = m0; break;                               \
            case 1: mat = vlo;   rb = m0; break;                               \
            case 2: mat = alnhi; rb = m0; break;                               \
            case 3: mat = alnlo; rb = m0; break;                               \
            case 4: mat = wxhi;  rb = n0; break;                               \
            case 5: mat = wxlo;  rb = n0; break;                               \
            case 6: mat = wyhi;  rb = n0; break;                               \
            default: mat = wylo; rb = n0; break;                               \
        }                                                                      \
        size_t g = (size_t)(rb + r) * DD + (kc) + cc * 8;                      \
        uint32_t dst = sbase + (uint32_t)tile * XT + (uint32_t)(r * 80 + cc * 16); \
        CP_ASYNC16(dst, (const void*)(mat + g));                               \
    }                                                                          \
} while (0)

    XY_ISSUE(0, 0);
    CP_COMMIT();

    for (int ch = 0; ch < 8; ch++) {
        if (ch + 1 < 8) {
            XY_ISSUE((ch + 1) & 1, (ch + 1) << 5);
            CP_COMMIT();
            CP_WAIT(1);
        } else {
            CP_WAIT(0);
        }
        __syncthreads();

        uint32_t S = sb + (uint32_t)(ch & 1) * XSTG;
#pragma unroll
        for (int ks = 0; ks < 2; ks++) {
            uint32_t arow_off = (uint32_t)(warp_m * 32 + a_row_l) * 80
                              + (uint32_t)(ks * 16 + a_col_l) * 2;
            uint32_t brow_off = (uint32_t)(warp_n * 64 + b_row_l) * 80
                              + (uint32_t)(ks * 16 + b_col_l) * 2;
            uint32_t ah[2][4], al[2][4], bh[8][2], bl[8][2];
            // ---- X: A = v, B = wx ----
#pragma unroll
            for (int mt = 0; mt < 2; mt++) {
                uint32_t ad = S + arow_off + (uint32_t)(mt * 16 * 80);
                LDSM_X4(ah[mt][0], ah[mt][1], ah[mt][2], ah[mt][3], ad);
                LDSM_X4(al[mt][0], al[mt][1], al[mt][2], al[mt][3], ad + XT);
            }
#pragma unroll
            for (int p = 0; p < 4; p++) {
                uint32_t bd = S + 4 * XT + brow_off + (uint32_t)(p * 16 * 80);
                uint32_t q0, q1, q2, q3;
                LDSM_X4(q0, q1, q2, q3, bd);
                bh[2 * p][0] = q0; bh[2 * p][1] = q1;
                bh[2 * p + 1][0] = q2; bh[2 * p + 1][1] = q3;
                LDSM_X4(q0, q1, q2, q3, bd + XT);
                bl[2 * p][0] = q0; bl[2 * p][1] = q1;
                bl[2 * p + 1][0] = q2; bl[2 * p + 1][1] = q3;
            }
#pragma unroll
            for (int mt = 0; mt < 2; mt++)
#pragma unroll
                for (int nt = 0; nt < 8; nt++)
                    MMA_BF16(accx[mt][nt], ah[mt], bh[nt]);
#pragma unroll
            for (int mt = 0; mt < 2; mt++)
#pragma unroll
                for (int nt = 0; nt < 8; nt++)
                    MMA_BF16(accx[mt][nt], ah[mt], bl[nt]);
#pragma unroll
            for (int mt = 0; mt < 2; mt++)
#pragma unroll
                for (int nt = 0; nt < 8; nt++)
                    MMA_BF16(accx[mt][nt], al[mt], bh[nt]);
            // ---- Y: A = aln, B = wy ----
#pragma unroll
            for (int mt = 0; mt < 2; mt++) {
                uint32_t ad = S + 2 * XT + arow_off + (uint32_t)(mt * 16 * 80);
                LDSM_X4(ah[mt][0], ah[mt][1], ah[mt][2], ah[mt][3], ad);
                LDSM_X4(al[mt][0], al[mt][1], al[mt][2], al[mt][3], ad + XT);
            }
#pragma unroll
            for (int p = 0; p < 4; p++) {
                uint32_t bd = S + 6 * XT + brow_off + (uint32_t)(p * 16 * 80);
                uint32_t q0, q1, q2, q3;
                LDSM_X4(q0, q1, q2, q3, bd);
                bh[2 * p][0] = q0; bh[2 * p][1] = q1;
                bh[2 * p + 1][0] = q2; bh[2 * p + 1][1] = q3;
                LDSM_X4(q0, q1, q2, q3, bd + XT);
                bl[2 * p][0] = q0; bl[2 * p][1] = q1;
                bl[2 * p + 1][0] = q2; bl[2 * p + 1][1] = q3;
            }
#pragma unroll
            for (int mt = 0; mt < 2; mt++)
#pragma unroll
                for (int nt = 0; nt < 8; nt++)
                    MMA_BF16(accy[mt][nt], ah[mt], bh[nt]);
#pragma unroll
            for (int mt = 0; mt < 2; mt++)
#pragma unroll
                for (int nt = 0; nt < 8; nt++)
                    MMA_BF16(accy[mt][nt], ah[mt], bl[nt]);
#pragma unroll
            for (int mt = 0; mt < 2; mt++)
#pragma unroll
                for (int nt = 0; nt < 8; nt++)
                    MMA_BF16(accy[mt][nt], al[mt], bh[nt]);
        }
        __syncthreads();
    }

    int tr = lane >> 2;
    int tc = (lane & 3) * 2;
#pragma unroll
    for (int mt = 0; mt < 2; mt++) {
        int row = m0 + warp_m * 32 + mt * 16 + tr;
#pragma unroll
        for (int nt = 0; nt < 8; nt++) {
            int col = n0 + warp_n * 64 + nt * 8 + tc;
            size_t i0 = (size_t)row * NN + col;
            size_t i1 = (size_t)(row + 8) * NN + col;
            float g0 = fmaxf(accx[mt][nt][0], 0.f) * fmaxf(accy[mt][nt][0], 0.f);
            float g1 = fmaxf(accx[mt][nt][1], 0.f) * fmaxf(accy[mt][nt][1], 0.f);
            float g2 = fmaxf(accx[mt][nt][2], 0.f) * fmaxf(accy[mt][nt][2], 0.f);
            float g3 = fmaxf(accx[mt][nt][3], 0.f) * fmaxf(accy[mt][nt][3], 0.f);
            __nv_bfloat16 h0, l0, h1, l1;
            split2(g0, h0, l0); split2(g1, h1, l1);
            *(__nv_bfloat162*)(Yhi + i0) = __halves2bfloat162(h0, h1);
            *(__nv_bfloat162*)(Ylo + i0) = __halves2bfloat162(l0, l1);
            split2(g2, h0, l0); split2(g3, h1, l1);
            *(__nv_bfloat162*)(Yhi + i1) = __halves2bfloat162(h0, h1);
            *(__nv_bfloat162*)(Ylo + i1) = __halves2bfloat162(l0, l1);
        }
    }
}

// ---------------- HMMA GEMM with cp.async double buffering ------------------
#define TILE_B 18432
#define STAGE_B (4 * TILE_B)
#define TCG_SMEM (2 * STAGE_B)
__global__ void __launch_bounds__(256, 1)
tc_gemm(const __nv_bfloat16* __restrict__ Ahi, const __nv_bfloat16* __restrict__ Alo,
        const __nv_bfloat16* __restrict__ Bhi, const __nv_bfloat16* __restrict__ Blo,
        int K, float* __restrict__ C, int ldc) {
    char* smc = dynsm;
    uint32_t sb = smem_u32(smc);

    int tid = threadIdx.x;
    int wid = tid >> 5;
    int lane = tid & 31;
    int warp_m = wid & 3;
    int warp_n = wid >> 2;

    int m0 = blockIdx.y * 128;
    int n0 = blockIdx.x * 128;

    float acc[2][8][4] = {};

    uint32_t a_row_l = (uint32_t)(lane & 15);
    uint32_t a_col_l = (uint32_t)((lane >> 4) << 3);
    uint32_t b_row_l = (uint32_t)(((lane & 16) >> 1) + (lane & 7));
    uint32_t b_col_l = (uint32_t)(lane & 8);

    int lr[4], lcc[4];
#pragma unroll
    for (int q = 0; q < 4; q++) {
        int l = tid + q * 256;
        lr[q] = l >> 3;
        lcc[q] = l & 7;
    }

    int nchunks = K >> 6;

    auto issue = [&](int st, int kc) {
        uint32_t sbase = sb + (uint32_t)st * STAGE_B;
#pragma unroll
        for (int q = 0; q < 4; q++) {
            int r = lr[q], c = lcc[q];
            uint32_t so = sbase + (uint32_t)(r * 144 + c * 16);
            size_t ga = (size_t)(m0 + r) * K + kc + c * 8;
            size_t gb = (size_t)(n0 + r) * K + kc + c * 8;
            CP_ASYNC16(so + 0 * TILE_B, (const void*)(Ahi + ga));
            CP_ASYNC16(so + 1 * TILE_B, (const void*)(Alo + ga));
            CP_ASYNC16(so + 2 * TILE_B, (const void*)(Bhi + gb));
            CP_ASYNC16(so + 3 * TILE_B, (const void*)(Blo + gb));
        }
    };

    issue(0, 0);
    CP_COMMIT();

    for (int ch = 0; ch < nchunks; ch++) {
        if (ch + 1 < nchunks) {
            issue((ch + 1) & 1, (ch + 1) << 6);
            CP_COMMIT();
            CP_WAIT(1);
        } else {
            CP_WAIT(0);
        }
        __syncthreads();

        uint32_t sA = sb + (uint32_t)(ch & 1) * STAGE_B;
        uint32_t sB = sA + 2 * TILE_B;
#pragma unroll
        for (int ks = 0; ks < 4; ks++) {
            uint32_t ah[2][4], al[2][4];
#pragma unroll
            for (int mt = 0; mt < 2; mt++) {
                uint32_t ad = sA + (uint32_t)(warp_m * 32 + mt * 16 + a_row_l) * 144
                            + (uint32_t)(ks * 16 + a_col_l) * 2;
                LDSM_X4(ah[mt][0], ah[mt][1], ah[mt][2], ah[mt][3], ad);
                LDSM_X4(al[mt][0], al[mt][1], al[mt][2], al[mt][3], ad + TILE_B);
            }
            uint32_t bh[8][2], bl[8][2];
#pragma unroll
            for (int p = 0; p < 4; p++) {
                uint32_t bd = sB + (uint32_t)(warp_n * 64 + p * 16 + b_row_l) * 144
                            + (uint32_t)(ks * 16 + b_col_l) * 2;
                uint32_t q0, q1, q2, q3;
                LDSM_X4(q0, q1, q2, q3, bd);
                bh[2 * p][0] = q0; bh[2 * p][1] = q1;
                bh[2 * p + 1][0] = q2; bh[2 * p + 1][1] = q3;
                LDSM_X4(q0, q1, q2, q3, bd + TILE_B);
                bl[2 * p][0] = q0; bl[2 * p][1] = q1;
                bl[2 * p + 1][0] = q2; bl[2 * p + 1][1] = q3;
            }
#pragma unroll
            for (int mt = 0; mt < 2; mt++)
#pragma unroll
                for (int nt = 0; nt < 8; nt++)
                    MMA_BF16(acc[mt][nt], ah[mt], bh[nt]);
#pragma unroll
            for (int mt = 0; mt < 2; mt++)
#pragma unroll
                for (int nt = 0; nt < 8; nt++)
                    MMA_BF16(acc[mt][nt], ah[mt], bl[nt]);
#pragma unroll
            for (int mt = 0; mt < 2; mt++)
#pragma unroll
                for (int nt = 0; nt < 8; nt++)
                    MMA_BF16(acc[mt][nt], al[mt], bh[nt]);
        }
        __syncthreads();
    }

    int tr = lane >> 2;
    int tc = (lane & 3) * 2;
#pragma unroll
    for (int mt = 0; mt < 2; mt++) {
        int row = m0 + warp_m * 32 + mt * 16 + tr;
#pragma unroll
        for (int nt = 0; nt < 8; nt++) {
            int col = n0 + warp_n * 64 + nt * 8 + tc;
            *(float2*)&C[(size_t)row * ldc + col] =
                make_float2(acc[mt][nt][0], acc[mt][nt][1]);
            *(float2*)&C[(size_t)(row + 8) * ldc + col] =
                make_float2(acc[mt][nt][2], acc[mt][nt][3]);
        }
    }
}

// ---------------- launch -----------------------------------------------------
extern "C" void kernel_launch(void* const* d_in, const int* in_sizes, int n_in,
                              void* d_out, int out_size) {
    const int* idx = (const int*)d_in[0];
    const float* wte = (const float*)d_in[1];
    const float* encoder = (const float*)d_in[2];
    const float* dec_x = (const float*)d_in[3];
    const float* dec_y = (const float*)d_in[4];
    const float* readout = (const float*)d_in[5];
    float* out = (float*)d_out;

    float *pv, *pR, *pa, *pu, *pH;
    __nv_bfloat16 *pvhi, *pvlo, *pRhi, *pRlo, *palnhi, *palnlo;
    __nv_bfloat16 *pwxhi, *pwxlo, *pwyhi, *pwylo, *penchi, *penclo, *prdhi, *prdlo;
    __nv_bfloat16 *pYhi, *pYlo, *pRThi, *pRTlo, *pVThi, *pVTlo, *pMhi, *pMlo;
    cudaGetSymbolAddress((void**)&pv, g_v);
    cudaGetSymbolAddress((void**)&pR, g_R);
    cudaGetSymbolAddress((void**)&pa, g_a);
    cudaGetSymbolAddress((void**)&pu, g_u);
    cudaGetSymbolAddress((void**)&pH, g_H);
    cudaGetSymbolAddress((void**)&pvhi, g_vhi);
    cudaGetSymbolAddress((void**)&pvlo, g_vlo);
    cudaGetSymbolAddress((void**)&pRhi, g_Rhi);
    cudaGetSymbolAddress((void**)&pRlo, g_Rlo);
    cudaGetSymbolAddress((void**)&palnhi, g_alnhi);
    cudaGetSymbolAddress((void**)&palnlo, g_alnlo);
    cudaGetSymbolAddress((void**)&pwxhi, g_wxhi);
    cudaGetSymbolAddress((void**)&pwxlo, g_wxlo);
    cudaGetSymbolAddress((void**)&pwyhi, g_wyhi);
    cudaGetSymbolAddress((void**)&pwylo, g_wylo);
    cudaGetSymbolAddress((void**)&penchi, g_enchi);
    cudaGetSymbolAddress((void**)&penclo, g_enclo);
    cudaGetSymbolAddress((void**)&prdhi, g_rdhi);
    cudaGetSymbolAddress((void**)&prdlo, g_rdlo);
    cudaGetSymbolAddress((void**)&pYhi, g_Yhi);
    cudaGetSymbolAddress((void**)&pYlo, g_Ylo);
    cudaGetSymbolAddress((void**)&pRThi, g_RThi);
    cudaGetSymbolAddress((void**)&pRTlo, g_RTlo);
    cudaGetSymbolAddress((void**)&pVThi, g_VThi);
    cudaGetSymbolAddress((void**)&pVTlo, g_VTlo);
    cudaGetSymbolAddress((void**)&pMhi, g_Mhi);
    cudaGetSymbolAddress((void**)&pMlo, g_Mlo);

    cudaFuncSetAttribute(tc_gemm,
                         cudaFuncAttributeMaxDynamicSharedMemorySize, TCG_SMEM);
    cudaFuncSetAttribute(xy_gemm,
                         cudaFuncAttributeMaxDynamicSharedMemorySize, XY_SMEM);
    cudaFuncSetAttribute(kv_outer_kernel,
                         cudaFuncAttributeMaxDynamicSharedMemorySize, KVO_SMEM);
    cudaFuncSetAttribute(attn_out_kernel,
                         cudaFuncAttributeMaxDynamicSharedMemorySize, AO_SMEM);

    conv_dec_kernel<<<(NN * DD) / 256, 256>>>(dec_x, pwxhi, pwxlo);
    conv_dec_kernel<<<(NN * DD) / 256, 256>>>(dec_y, pwyhi, pwylo);
    conv_enc_kernel<<<(DD * NN) / 256, 256>>>(encoder, penchi, penclo);
    conv_rd_kernel<<<(VOCAB * DD) / 256, 256>>>(readout, prdhi, prdlo);

    embed_ln_rope_kernel<<<BT, 256>>>(idx, wte, pv, pvhi, pvlo, pR, pRhi, pRlo);

    for (int layer = 0; layer < LL; layer++) {
        // attention (chunked linear form); R prepared by previous ln_add_rope
        split_T_kernel<<<dim3(TT / 32, DD / 32, BB), 256>>>(pR, pRThi, pRTlo);
        split_T_kernel<<<dim3(TT / 32, DD / 32, BB), 256>>>(pv, pVThi, pVTlo);
        kv_outer_kernel<<<dim3(32, BB, 2), 512, KVO_SMEM>>>(pVThi, pVTlo,
                                                            pRThi, pRTlo, pH);
        prefix_split_kernel<<<dim3(256, BB), 256>>>(pH, pMhi, pMlo);
        attn_out_kernel<<<dim3(32, BB), 256, AO_SMEM>>>(pRhi, pRlo, pVThi, pVTlo,
                                                        pMhi, pMlo, pa);
        ln_split_kernel<<<BT, 256>>>(pa, palnhi, palnlo);

        // fused X/Y GEMM + gate -> Y hi/lo
        xy_gemm<<<dim3(NN / 128, BT / 128), 256, XY_SMEM>>>(
            pvhi, pvlo, palnhi, palnlo, pwxhi, pwxlo, pwyhi, pwylo, pYhi, pYlo);
        // u = Y @ encoder
        tc_gemm<<<dim3(DD / 128, BT / 128), 256, TCG_SMEM>>>(
            pYhi, pYlo, penchi, penclo, NN, pu, DD);
        // v += LN(u); also compute RoPE for next layer
        ln_add_rope_kernel<<<BT, 256>>>(pu, pv, pvhi, pvlo, pR, pRhi, pRlo);
    }

    // logits = v @ readout
    tc_gemm<<<dim3(VOCAB / 128, BT / 128), 256, TCG_SMEM>>>(
        pvhi, pvlo, prdhi, prdlo, DD, out, VOCAB);
}

// round 7
// speedup vs baseline: 6.4762x; 1.0020x over previous
#include <cuda_runtime.h>
#include <cuda_bf16.h>
#include <math.h>
#include <stdint.h>

// Problem constants
#define BB 4
#define TT 2048
#define BT 8192      // B*T
#define DD 256
#define NN 8192
#define HH 4
#define MM 2048      // N/H
#define LL 6
#define VOCAB 256
#define EPS 1e-5f

// single dynamic-smem declaration shared by all kernels
extern __shared__ char dynsm[];

// ---------------- scratch buffers (device globals, no allocations) --------
__device__ float g_v[BT * DD];
__device__ float g_R[BT * DD];
__device__ float g_upart[4 * BT * DD];                        // split-K partials
__device__ __nv_bfloat16 g_vhi[BT * DD], g_vlo[BT * DD];
__device__ __nv_bfloat16 g_Rhi[BT * DD], g_Rlo[BT * DD];
__device__ __nv_bfloat16 g_alnhi[BT * DD], g_alnlo[BT * DD];
__device__ __nv_bfloat16 g_wxhi[NN * DD], g_wxlo[NN * DD];
__device__ __nv_bfloat16 g_wyhi[NN * DD], g_wylo[NN * DD];
__device__ __nv_bfloat16 g_enchi[DD * NN], g_enclo[DD * NN];
__device__ __nv_bfloat16 g_rdhi[VOCAB * DD], g_rdlo[VOCAB * DD];
__device__ __nv_bfloat16 g_Yhi[(size_t)BT * NN];              // 128 MB
__device__ __nv_bfloat16 g_Ylo[(size_t)BT * NN];              // 128 MB
// linear-attention scratch
__device__ __nv_bfloat16 g_RThi[BB * DD * TT], g_RTlo[BB * DD * TT];
__device__ __nv_bfloat16 g_VThi[BB * DD * TT], g_VTlo[BB * DD * TT];
__device__ float g_H[(size_t)BB * 32 * DD * DD];
__device__ __nv_bfloat16 g_Mhi[(size_t)BB * 32 * DD * DD];
__device__ __nv_bfloat16 g_Mlo[(size_t)BB * 32 * DD * DD];

// ---------------- PTX helpers ----------------------------------------------
__device__ __forceinline__ uint32_t smem_u32(const void* p) {
    uint32_t a;
    asm("{ .reg .u64 t; cvta.to.shared.u64 t, %1; cvt.u32.u64 %0, t; }"
        : "=r"(a) : "l"(p));
    return a;
}

#define LDSM_X4(r0, r1, r2, r3, addr) \
    asm volatile("ldmatrix.sync.aligned.m8n8.x4.shared.b16 {%0,%1,%2,%3}, [%4];" \
        : "=r"(r0), "=r"(r1), "=r"(r2), "=r"(r3) : "r"(addr))

#define MMA_BF16(d, a, b) \
    asm volatile( \
        "mma.sync.aligned.m16n8k16.row.col.f32.bf16.bf16.f32 " \
        "{%0,%1,%2,%3}, {%4,%5,%6,%7}, {%8,%9}, {%0,%1,%2,%3};" \
        : "+f"((d)[0]), "+f"((d)[1]), "+f"((d)[2]), "+f"((d)[3]) \
        : "r"((a)[0]), "r"((a)[1]), "r"((a)[2]), "r"((a)[3]), \
          "r"((b)[0]), "r"((b)[1]))

#define CP_ASYNC16(dst, src) \
    asm volatile("cp.async.cg.shared.global [%0], [%1], 16;" \
        :: "r"(dst), "l"(src) : "memory")
#define CP_COMMIT() asm volatile("cp.async.commit_group;" ::: "memory")
#define CP_WAIT(N)  asm volatile("cp.async.wait_group %0;" :: "n"(N) : "memory")

// ---------------- misc helpers ----------------------------------------------
__device__ __forceinline__ float warp_sum(float v) {
#pragma unroll
    for (int o = 16; o > 0; o >>= 1) v += __shfl_xor_sync(0xffffffffu, v, o);
    return v;
}
__device__ __forceinline__ void split2(float x, __nv_bfloat16& h, __nv_bfloat16& l) {
    __nv_bfloat16 hh = __float2bfloat16(x);
    h = hh;
    l = __float2bfloat16(x - __bfloat162float(hh));
}
__device__ __forceinline__ float rope_val(const float* rowbuf, int d, int t) {
    float x = rowbuf[d];
    float xr = (d < 128) ? -rowbuf[d + 128] : rowbuf[d - 128];
    int j = d & 127;
    float inv = expf(-(float)j * (2.f / 256.f) * 9.210340371976184f);
    float ang = (float)t * inv;
    const float TWO_PI_HI = 6.28318548202514648f;
    const float TWO_PI_LO = -1.74845553e-7f;
    float k = rintf(ang * 0.15915494309189535f);
    float r = fmaf(-k, TWO_PI_HI, ang);
    r = fmaf(-k, TWO_PI_LO, r);
    float sn = sinf(r), cs = cosf(r);
    return x * cs + xr * sn;
}

// ---------------- all weight conversions in one kernel ----------------------
__global__ void conv_all_kernel(const float* __restrict__ dec_x,
                                const float* __restrict__ dec_y,
                                const float* __restrict__ enc,
                                const float* __restrict__ rd,
                                __nv_bfloat16* __restrict__ wxhi, __nv_bfloat16* __restrict__ wxlo,
                                __nv_bfloat16* __restrict__ wyhi, __nv_bfloat16* __restrict__ wylo,
                                __nv_bfloat16* __restrict__ enchi, __nv_bfloat16* __restrict__ enclo,
                                __nv_bfloat16* __restrict__ rdhi, __nv_bfloat16* __restrict__ rdlo) {
    int bid = blockIdx.x;
    if (bid < 8192) {
        size_t i = (size_t)bid * 256 + threadIdx.x;
        int d = (int)(i & 255);
        size_t n = i >> 8;
        int h = (int)(n >> 11), m = (int)(n & 2047);
        split2(dec_x[((size_t)h * DD + d) * MM + m], wxhi[i], wxlo[i]);
    } else if (bid < 16384) {
        size_t i = (size_t)(bid - 8192) * 256 + threadIdx.x;
        int d = (int)(i & 255);
        size_t n = i >> 8;
        int h = (int)(n >> 11), m = (int)(n & 2047);
        split2(dec_y[((size_t)h * DD + d) * MM + m], wyhi[i], wylo[i]);
    } else if (bid < 24576) {
        size_t i = (size_t)(bid - 16384) * 256 + threadIdx.x;
        int n = (int)(i & 8191);
        int d = (int)(i >> 13);
        split2(enc[(size_t)n * DD + d], enchi[i], enclo[i]);
    } else {
        size_t i = (size_t)(bid - 24576) * 256 + threadIdx.x;
        int d = (int)(i & 255);
        int v = (int)(i >> 8);
        split2(rd[(size_t)d * VOCAB + v], rdhi[i], rdlo[i]);
    }
}

// ---------------- embed + LN + RoPE ------------------------------------------
__global__ void embed_ln_rope_kernel(const int* __restrict__ idx,
                                     const float* __restrict__ wte,
                                     float* __restrict__ out,
                                     __nv_bfloat16* __restrict__ ohi,
                                     __nv_bfloat16* __restrict__ olo,
                                     float* __restrict__ R,
                                     __nv_bfloat16* __restrict__ Rhi,
                                     __nv_bfloat16* __restrict__ Rlo) {
    __shared__ float sh[8];
    __shared__ float rowbuf[256];
    int row = blockIdx.x;
    int d = threadIdx.x;
    float x = wte[idx[row] * DD + d];
    int wid = d >> 5, lane = d & 31;
    float s = warp_sum(x);
    if (lane == 0) sh[wid] = s;
    __syncthreads();
    float tot = 0.f;
#pragma unroll
    for (int i = 0; i < 8; i++) tot += sh[i];
    float mu = tot * (1.f / 256.f);
    __syncthreads();
    float dx = x - mu;
    s = warp_sum(dx * dx);
    if (lane == 0) sh[wid] = s;
    __syncthreads();
    tot = 0.f;
#pragma unroll
    for (int i = 0; i < 8; i++) tot += sh[i];
    float r = dx * rsqrtf(tot * (1.f / 256.f) + EPS);
    out[row * DD + d] = r;
    split2(r, ohi[row * DD + d], olo[row * DD + d]);
    rowbuf[d] = r;
    __syncthreads();
    float val = rope_val(rowbuf, d, row & (TT - 1));
    R[row * DD + d] = val;
    split2(val, Rhi[row * DD + d], Rlo[row * DD + d]);
}

// ---------------- LN + residual add (sums 4 split-K partials) + RoPE --------
__global__ void ln_add_rope_kernel(const float* __restrict__ up,
                                   float* __restrict__ v,
                                   __nv_bfloat16* __restrict__ vhi,
                                   __nv_bfloat16* __restrict__ vlo,
                                   float* __restrict__ R,
                                   __nv_bfloat16* __restrict__ Rhi,
                                   __nv_bfloat16* __restrict__ Rlo) {
    __shared__ float sh[8];
    __shared__ float rowbuf[256];
    int row = blockIdx.x;
    int d = threadIdx.x;
    int o = row * DD + d;
    float x = up[o] + up[BT * DD + o] + up[2 * BT * DD + o] + up[3 * BT * DD + o];
    int wid = d >> 5, lane = d & 31;
    float s = warp_sum(x);
    if (lane == 0) sh[wid] = s;
    __syncthreads();
    float tot = 0.f;
#pragma unroll
    for (int i = 0; i < 8; i++) tot += sh[i];
    float mu = tot * (1.f / 256.f);
    __syncthreads();
    float dx = x - mu;
    s = warp_sum(dx * dx);
    if (lane == 0) sh[wid] = s;
    __syncthreads();
    tot = 0.f;
#pragma unroll
    for (int i = 0; i < 8; i++) tot += sh[i];
    float nv = v[o] + dx * rsqrtf(tot * (1.f / 256.f) + EPS);
    v[o] = nv;
    split2(nv, vhi[o], vlo[o]);
    rowbuf[d] = nv;
    __syncthreads();
    float val = rope_val(rowbuf, d, row & (TT - 1));
    R[o] = val;
    split2(val, Rhi[o], Rlo[o]);
}

// ---------------- transpose + split for BOTH R and v in one launch ----------
__global__ void split_T_both_kernel(const float* __restrict__ Rg,
                                    const float* __restrict__ vg,
                                    __nv_bfloat16* __restrict__ RThi,
                                    __nv_bfloat16* __restrict__ RTlo,
                                    __nv_bfloat16* __restrict__ VThi,
                                    __nv_bfloat16* __restrict__ VTlo) {
    __shared__ float tile[32][33];
    int zb = blockIdx.z;
    int b = zb & 3;
    const float* in = (zb < 4) ? Rg : vg;
    __nv_bfloat16* hi = (zb < 4) ? RThi : VThi;
    __nv_bfloat16* lo = (zb < 4) ? RTlo : VTlo;
    int t0 = blockIdx.x * 32;
    int d0 = blockIdx.y * 32;
    int tx = threadIdx.x & 31, ty = threadIdx.x >> 5;
#pragma unroll
    for (int i = 0; i < 4; i++) {
        int t = ty + i * 8;
        tile[t][tx] = in[((size_t)(b * TT + t0 + t)) * DD + d0 + tx];
    }
    __syncthreads();
#pragma unroll
    for (int i = 0; i < 4; i++) {
        int d = ty + i * 8;
        float x = tile[tx][d];
        size_t o = ((size_t)(b * DD + d0 + d)) * TT + t0 + tx;
        split2(x, hi[o], lo[o]);
    }
}

// ---------------- kv_outer: H[b][i] = V_i^T K_i (256x256, k=64) -------------
#define KVO_SMEM 110592
__global__ void __launch_bounds__(512, 1)
kv_outer_kernel(const __nv_bfloat16* __restrict__ VThi,
                const __nv_bfloat16* __restrict__ VTlo,
                const __nv_bfloat16* __restrict__ RThi,
                const __nv_bfloat16* __restrict__ RTlo,
                float* __restrict__ H) {
    char* smc = dynsm;
    uint32_t sb = smem_u32(smc);
    int i = blockIdx.x, b = blockIdx.y, e0 = blockIdx.z * 128;
    int s0 = i * 64;
    int tid = threadIdx.x;
    int wid = tid >> 5, lane = tid & 31;
    int wm = wid & 3, wn = wid >> 2;

    for (int l = tid; l < 1024; l += 512) {
        int r = l >> 3, c = l & 7;
        size_t g = ((size_t)(b * DD + e0 + r)) * TT + s0 + c * 8;
        uint32_t so = (uint32_t)(r * 144 + c * 16);
        *(uint4*)(smc + so) = *(const uint4*)(VThi + g);
        *(uint4*)(smc + 18432 + so) = *(const uint4*)(VTlo + g);
    }
    for (int l = tid; l < 2048; l += 512) {
        int r = l >> 3, c = l & 7;
        size_t g = ((size_t)(b * DD + r)) * TT + s0 + c * 8;
        uint32_t so = (uint32_t)(36864 + r * 144 + c * 16);
        *(uint4*)(smc + so) = *(const uint4*)(RThi + g);
        *(uint4*)(smc + 36864 + so) = *(const uint4*)(RTlo + g);
    }
    __syncthreads();

    uint32_t a_row_l = (uint32_t)(lane & 15);
    uint32_t a_col_l = (uint32_t)((lane >> 4) << 3);
    uint32_t b_row_l = (uint32_t)(((lane & 16) >> 1) + (lane & 7));
    uint32_t b_col_l = (uint32_t)(lane & 8);

    float acc[2][8][4] = {};
#pragma unroll
    for (int ks = 0; ks < 4; ks++) {
        uint32_t ah[2][4], al[2][4];
#pragma unroll
        for (int mi = 0; mi < 2; mi++) {
            uint32_t ad = sb + (uint32_t)(wm * 32 + mi * 16 + a_row_l) * 144
                        + (uint32_t)(ks * 16 + a_col_l) * 2;
            LDSM_X4(ah[mi][0], ah[mi][1], ah[mi][2], ah[mi][3], ad);
            LDSM_X4(al[mi][0], al[mi][1], al[mi][2], al[mi][3], ad + 18432);
        }
        uint32_t bh[8][2], bl[8][2];
#pragma unroll
        for (int p = 0; p < 4; p++) {
            uint32_t bd = sb + 36864 + (uint32_t)(wn * 64 + p * 16 + b_row_l) * 144
                        + (uint32_t)(ks * 16 + b_col_l) * 2;
            uint32_t q0, q1, q2, q3;
            LDSM_X4(q0, q1, q2, q3, bd);
            bh[2 * p][0] = q0; bh[2 * p][1] = q1;
            bh[2 * p + 1][0] = q2; bh[2 * p + 1][1] = q3;
            LDSM_X4(q0, q1, q2, q3, bd + 36864);
            bl[2 * p][0] = q0; bl[2 * p][1] = q1;
            bl[2 * p + 1][0] = q2; bl[2 * p + 1][1] = q3;
        }
#pragma unroll
        for (int mi = 0; mi < 2; mi++)
#pragma unroll
            for (int nt = 0; nt < 8; nt++)
                MMA_BF16(acc[mi][nt], ah[mi], bh[nt]);
#pragma unroll
        for (int mi = 0; mi < 2; mi++)
#pragma unroll
            for (int nt = 0; nt < 8; nt++)
                MMA_BF16(acc[mi][nt], ah[mi], bl[nt]);
#pragma unroll
        for (int mi = 0; mi < 2; mi++)
#pragma unroll
            for (int nt = 0; nt < 8; nt++)
                MMA_BF16(acc[mi][nt], al[mi], bh[nt]);
    }

    int tr = lane >> 2, tc = (lane & 3) * 2;
    size_t base = ((size_t)(b * 32 + i)) * 65536;
#pragma unroll
    for (int mi = 0; mi < 2; mi++) {
        int e = e0 + wm * 32 + mi * 16 + tr;
#pragma unroll
        for (int nt = 0; nt < 8; nt++) {
            int d = wn * 64 + nt * 8 + tc;
            *(float2*)&H[base + (size_t)e * 256 + d] =
                make_float2(acc[mi][nt][0], acc[mi][nt][1]);
            *(float2*)&H[base + (size_t)(e + 8) * 256 + d] =
                make_float2(acc[mi][nt][2], acc[mi][nt][3]);
        }
    }
}

// ---------------- exclusive prefix over chunks + bf16 split -----------------
__global__ void prefix_split_kernel(const float* __restrict__ H,
                                    __nv_bfloat16* __restrict__ Mhi,
                                    __nv_bfloat16* __restrict__ Mlo) {
    int b = blockIdx.y;
    int j = blockIdx.x * 256 + threadIdx.x;
    size_t base = (size_t)b * 32 * 65536 + j;
    float acc = 0.f;
#pragma unroll 4
    for (int i = 0; i < 32; i++) {
        size_t off = base + (size_t)i * 65536;
        __nv_bfloat16 h, l;
        split2(acc, h, l);
        Mhi[off] = h;
        Mlo[off] = l;
        acc += H[off];
    }
}

// ---------------- attn_out + fused row-LN ------------------------------------
// O_i = Q_i M_i + tril(Q_i K_i^T) V_i ; then aln = LN(O) -> hi/lo (bf16)
#define AO_Q    0
#define AO_QLO  33792
#define AO_B    67584
#define AO_BLO  104448
#define AO_S    141312
#define AO_SLO  150528
#define AO_OBUF 67584          // fp32 64 x 260 (reuses B region post-MMA)
#define AO_SMEM 159744
__global__ void __launch_bounds__(256, 1)
attn_out_kernel(const __nv_bfloat16* __restrict__ Rhi,
                const __nv_bfloat16* __restrict__ Rlo,
                const __nv_bfloat16* __restrict__ VThi,
                const __nv_bfloat16* __restrict__ VTlo,
                const __nv_bfloat16* __restrict__ Mhi,
                const __nv_bfloat16* __restrict__ Mlo,
                __nv_bfloat16* __restrict__ alnhi,
                __nv_bfloat16* __restrict__ alnlo) {
    char* smc = dynsm;
    uint32_t sb = smem_u32(smc);
    int i = blockIdx.x, b = blockIdx.y;
    int q0 = i * 64;
    int tid = threadIdx.x;
    int wid = tid >> 5, lane = tid & 31;

    for (int l = tid; l < 2048; l += 256) {
        int r = l >> 5, c = l & 31;
        size_t g = ((size_t)(b * TT + q0 + r)) * DD + c * 8;
        uint32_t so = (uint32_t)(r * 528 + c * 16);
        *(uint4*)(smc + AO_Q + so) = *(const uint4*)(Rhi + g);
        *(uint4*)(smc + AO_QLO + so) = *(const uint4*)(Rlo + g);
    }
    for (int l = tid; l < 2048; l += 256) {
        int r = l >> 3, c = l & 7;
        size_t g = ((size_t)(b * DD + r)) * TT + q0 + c * 8;
        uint32_t so = (uint32_t)(r * 144 + c * 16);
        *(uint4*)(smc + AO_B + so) = *(const uint4*)(VThi + g);
        *(uint4*)(smc + AO_BLO + so) = *(const uint4*)(VTlo + g);
    }
    __syncthreads();

    uint32_t a_row_l = (uint32_t)(lane & 15);
    uint32_t a_col_l = (uint32_t)((lane >> 4) << 3);
    uint32_t b_row_l = (uint32_t)(((lane & 16) >> 1) + (lane & 7));
    uint32_t b_col_l = (uint32_t)(lane & 8);
    int tr = lane >> 2, tc = (lane & 3) * 2;

    int wt = wid & 1, ws = wid >> 1;
    {
        float sacc[2][2][4] = {};
#pragma unroll
        for (int ks = 0; ks < 16; ks++) {
            uint32_t ah[2][4], al[2][4];
#pragma unroll
            for (int mi = 0; mi < 2; mi++) {
                uint32_t ad = sb + AO_Q + (uint32_t)(wt * 32 + mi * 16 + a_row_l) * 528
                            + (uint32_t)(ks * 16 + a_col_l) * 2;
                LDSM_X4(ah[mi][0], ah[mi][1], ah[mi][2], ah[mi][3], ad);
                LDSM_X4(al[mi][0], al[mi][1], al[mi][2], al[mi][3], ad + 33792);
            }
            uint32_t bh[2][2], bl[2][2];
            {
                uint32_t bd = sb + AO_Q + (uint32_t)(ws * 16 + b_row_l) * 528
                            + (uint32_t)(ks * 16 + b_col_l) * 2;
                uint32_t p0, p1, p2, p3;
                LDSM_X4(p0, p1, p2, p3, bd);
                bh[0][0] = p0; bh[0][1] = p1; bh[1][0] = p2; bh[1][1] = p3;
                LDSM_X4(p0, p1, p2, p3, bd + 33792);
                bl[0][0] = p0; bl[0][1] = p1; bl[1][0] = p2; bl[1][1] = p3;
            }
#pragma unroll
            for (int mi = 0; mi < 2; mi++)
#pragma unroll
                for (int ni = 0; ni < 2; ni++) {
                    MMA_BF16(sacc[mi][ni], ah[mi], bh[ni]);
                    MMA_BF16(sacc[mi][ni], ah[mi], bl[ni]);
                    MMA_BF16(sacc[mi][ni], al[mi], bh[ni]);
                }
        }
#pragma unroll
        for (int mi = 0; mi < 2; mi++)
#pragma unroll
            for (int ni = 0; ni < 2; ni++) {
                int t0l = wt * 32 + mi * 16 + tr;
                int sl = ws * 16 + ni * 8 + tc;
                float s0v = (sl > t0l) ? 0.f : sacc[mi][ni][0];
                float s1v = (sl + 1 > t0l) ? 0.f : sacc[mi][ni][1];
                float s2v = (sl > t0l + 8) ? 0.f : sacc[mi][ni][2];
                float s3v = (sl + 1 > t0l + 8) ? 0.f : sacc[mi][ni][3];
                __nv_bfloat16 h0, l0, h1, l1;
                split2(s0v, h0, l0); split2(s1v, h1, l1);
                *(__nv_bfloat162*)(smc + AO_S + t0l * 144 + sl * 2) = __halves2bfloat162(h0, h1);
                *(__nv_bfloat162*)(smc + AO_SLO + t0l * 144 + sl * 2) = __halves2bfloat162(l0, l1);
                split2(s2v, h0, l0); split2(s3v, h1, l1);
                *(__nv_bfloat162*)(smc + AO_S + (t0l + 8) * 144 + sl * 2) = __halves2bfloat162(h0, h1);
                *(__nv_bfloat162*)(smc + AO_SLO + (t0l + 8) * 144 + sl * 2) = __halves2bfloat162(l0, l1);
            }
    }
    __syncthreads();

    int we = wid >> 1;
    float oacc[2][8][4] = {};
#pragma unroll
    for (int ks = 0; ks < 4; ks++) {
        uint32_t ah[2][4], al[2][4];
#pragma unroll
        for (int mi = 0; mi < 2; mi++) {
            uint32_t ad = sb + AO_S + (uint32_t)(wt * 32 + mi * 16 + a_row_l) * 144
                        + (uint32_t)(ks * 16 + a_col_l) * 2;
            LDSM_X4(ah[mi][0], ah[mi][1], ah[mi][2], ah[mi][3], ad);
            LDSM_X4(al[mi][0], al[mi][1], al[mi][2], al[mi][3], ad + 9216);
        }
        uint32_t bh[8][2], bl[8][2];
#pragma unroll
        for (int p = 0; p < 4; p++) {
            uint32_t bd = sb + AO_B + (uint32_t)(we * 64 + p * 16 + b_row_l) * 144
                        + (uint32_t)(ks * 16 + b_col_l) * 2;
            uint32_t p0, p1, p2, p3;
            LDSM_X4(p0, p1, p2, p3, bd);
            bh[2 * p][0] = p0; bh[2 * p][1] = p1;
            bh[2 * p + 1][0] = p2; bh[2 * p + 1][1] = p3;
            LDSM_X4(p0, p1, p2, p3, bd + 36864);
            bl[2 * p][0] = p0; bl[2 * p][1] = p1;
            bl[2 * p + 1][0] = p2; bl[2 * p + 1][1] = p3;
        }
#pragma unroll
        for (int mi = 0; mi < 2; mi++)
#pragma unroll
            for (int nt = 0; nt < 8; nt++) {
                MMA_BF16(oacc[mi][nt], ah[mi], bh[nt]);
                MMA_BF16(oacc[mi][nt], ah[mi], bl[nt]);
                MMA_BF16(oacc[mi][nt], al[mi], bh[nt]);
            }
    }
    __syncthreads();

    size_t mbase = ((size_t)(b * 32 + i)) * 65536;
    for (int dc = 0; dc < 4; dc++) {
        for (int l = tid; l < 2048; l += 256) {
            int r = l >> 3, c = l & 7;
            size_t g = mbase + (size_t)r * 256 + dc * 64 + c * 8;
            uint32_t so = (uint32_t)(r * 144 + c * 16);
            *(uint4*)(smc + AO_B + so) = *(const uint4*)(Mhi + g);
            *(uint4*)(smc + AO_BLO + so) = *(const uint4*)(Mlo + g);
        }
        __syncthreads();
#pragma unroll
        for (int ks = 0; ks < 4; ks++) {
            int ksg = dc * 4 + ks;
            uint32_t ah[2][4], al[2][4];
#pragma unroll
            for (int mi = 0; mi < 2; mi++) {
                uint32_t ad = sb + AO_Q + (uint32_t)(wt * 32 + mi * 16 + a_row_l) * 528
                            + (uint32_t)(ksg * 16 + a_col_l) * 2;
                LDSM_X4(ah[mi][0], ah[mi][1], ah[mi][2], ah[mi][3], ad);
                LDSM_X4(al[mi][0], al[mi][1], al[mi][2], al[mi][3], ad + 33792);
            }
            uint32_t bh[8][2], bl[8][2];
#pragma unroll
            for (int p = 0; p < 4; p++) {
                uint32_t bd = sb + AO_B + (uint32_t)(we * 64 + p * 16 + b_row_l) * 144
                            + (uint32_t)(ks * 16 + b_col_l) * 2;
                uint32_t p0, p1, p2, p3;
                LDSM_X4(p0, p1, p2, p3, bd);
                bh[2 * p][0] = p0; bh[2 * p][1] = p1;
                bh[2 * p + 1][0] = p2; bh[2 * p + 1][1] = p3;
                LDSM_X4(p0, p1, p2, p3, bd + 36864);
                bl[2 * p][0] = p0; bl[2 * p][1] = p1;
                bl[2 * p + 1][0] = p2; bl[2 * p + 1][1] = p3;
            }
#pragma unroll
            for (int mi = 0; mi < 2; mi++)
#pragma unroll
                for (int nt = 0; nt < 8; nt++) {
                    MMA_BF16(oacc[mi][nt], ah[mi], bh[nt]);
                    MMA_BF16(oacc[mi][nt], ah[mi], bl[nt]);
                    MMA_BF16(oacc[mi][nt], al[mi], bh[nt]);
                }
        }
        __syncthreads();
    }

    // ---- fused LN epilogue: O -> smem, per-row LN, write aln hi/lo ----
    float* obuf = (float*)(smc + AO_OBUF);
#pragma unroll
    for (int mi = 0; mi < 2; mi++) {
        int rl = wt * 32 + mi * 16 + tr;
#pragma unroll
        for (int nt = 0; nt < 8; nt++) {
            int col = we * 64 + nt * 8 + tc;
            obuf[rl * 260 + col] = oacc[mi][nt][0];
            obuf[rl * 260 + col + 1] = oacc[mi][nt][1];
            obuf[(rl + 8) * 260 + col] = oacc[mi][nt][2];
            obuf[(rl + 8) * 260 + col + 1] = oacc[mi][nt][3];
        }
    }
    __syncthreads();

    for (int rr2 = 0; rr2 < 8; rr2++) {
        int r = wid * 8 + rr2;
        float vals[8];
        float s = 0.f;
#pragma unroll
        for (int k = 0; k < 8; k++) {
            vals[k] = obuf[r * 260 + lane + 32 * k];
            s += vals[k];
        }
        s = warp_sum(s);
        float mu = s * (1.f / 256.f);
        float q = 0.f;
#pragma unroll
        for (int k = 0; k < 8; k++) {
            float dxx = vals[k] - mu;
            q += dxx * dxx;
        }
        q = warp_sum(q);
        float rstd = rsqrtf(q * (1.f / 256.f) + EPS);
        size_t gbase = ((size_t)(b * TT + q0 + r)) * DD;
#pragma unroll
        for (int k = 0; k < 8; k++) {
            __nv_bfloat16 h, l;
            split2((vals[k] - mu) * rstd, h, l);
            alnhi[gbase + lane + 32 * k] = h;
            alnlo[gbase + lane + 32 * k] = l;
        }
    }
}

// ---------------- fused XY GEMM ----------------------------------------------
#define XT 10240
#define XSTG (8 * XT)
#define XY_SMEM (2 * XSTG)
__global__ void __launch_bounds__(256, 1)
xy_gemm(const __nv_bfloat16* __restrict__ vhi, const __nv_bfloat16* __restrict__ vlo,
        const __nv_bfloat16* __restrict__ alnhi, const __nv_bfloat16* __restrict__ alnlo,
        const __nv_bfloat16* __restrict__ wxhi, const __nv_bfloat16* __restrict__ wxlo,
        const __nv_bfloat16* __restrict__ wyhi, const __nv_bfloat16* __restrict__ wylo,
        __nv_bfloat16* __restrict__ Yhi, __nv_bfloat16* __restrict__ Ylo) {
    char* smc = dynsm;
    uint32_t sb = smem_u32(smc);

    int tid = threadIdx.x;
    int wid = tid >> 5;
    int lane = tid & 31;
    int warp_m = wid & 3;
    int warp_n = wid >> 2;

    int m0 = blockIdx.y * 128;
    int n0 = blockIdx.x * 128;

    float accx[2][8][4] = {};
    float accy[2][8][4] = {};

    uint32_t a_row_l = (uint32_t)(lane & 15);
    uint32_t a_col_l = (uint32_t)((lane >> 4) << 3);
    uint32_t b_row_l = (uint32_t)(((lane & 16) >> 1) + (lane & 7));
    uint32_t b_col_l = (uint32_t)(lane & 8);

    int rr = tid >> 2;
    int cc = tid & 3;

#define XY_ISSUE(st, kc) do {                                                  \
    uint32_t sbase = sb + (uint32_t)(st) * XSTG;                               \
    _Pragma("unroll")                                                          \
    for (int q = 0; q < 16; q++) {                                             \
        int tile = q >> 1;                                                     \
        int r = ((q & 1) << 6) + rr;                                           \
        const __nv_bfloat16* mat;                                              \
        int rb;                                                                \
        switch (tile) {                                                        \
            case 0: mat = vhi;   rb = m0; break;                               \
            case 1: mat = vlo;   rb = m0; break;                               \
            case 2: mat = alnhi; rb = m0; break;                               \
            case 3: mat = alnlo; rb = m0; break;                               \
            case 4: mat = wxhi;  rb = n0; break;                               \
            case 5: mat = wxlo;  rb = n0; break;                               \
            case 6: mat = wyhi;  rb = n0; break;                               \
            default: mat = wylo; rb = n0; break;                               \
        }                                                                      \
        size_t g = (size_t)(rb + r) * DD + (kc) + cc * 8;                      \
        uint32_t dst = sbase + (uint32_t)tile * XT + (uint32_t)(r * 80 + cc * 16); \
        CP_ASYNC16(dst, (const void*)(mat + g));                               \
    }                                                                          \
} while (0)

    XY_ISSUE(0, 0);
    CP_COMMIT();

    for (int ch = 0; ch < 8; ch++) {
        if (ch + 1 < 8) {
            XY_ISSUE((ch + 1) & 1, (ch + 1) << 5);
            CP_COMMIT();
            CP_WAIT(1);
        } else {
            CP_WAIT(0);
        }
        __syncthreads();

        uint32_t S = sb + (uint32_t)(ch & 1) * XSTG;
#pragma unroll
        for (int ks = 0; ks < 2; ks++) {
            uint32_t arow_off = (uint32_t)(warp_m * 32 + a_row_l) * 80
                              + (uint32_t)(ks * 16 + a_col_l) * 2;
            uint32_t brow_off = (uint32_t)(warp_n * 64 + b_row_l) * 80
                              + (uint32_t)(ks * 16 + b_col_l) * 2;
            uint32_t ah[2][4], al[2][4], bh[8][2], bl[8][2];
#pragma unroll
            for (int mt = 0; mt < 2; mt++) {
                uint32_t ad = S + arow_off + (uint32_t)(mt * 16 * 80);
                LDSM_X4(ah[mt][0], ah[mt][1], ah[mt][2], ah[mt][3], ad);
                LDSM_X4(al[mt][0], al[mt][1], al[mt][2], al[mt][3], ad + XT);
            }
#pragma unroll
            for (int p = 0; p < 4; p++) {
                uint32_t bd = S + 4 * XT + brow_off + (uint32_t)(p * 16 * 80);
                uint32_t q0, q1, q2, q3;
                LDSM_X4(q0, q1, q2, q3, bd);
                bh[2 * p][0] = q0; bh[2 * p][1] = q1;
                bh[2 * p + 1][0] = q2; bh[2 * p + 1][1] = q3;
                LDSM_X4(q0, q1, q2, q3, bd + XT);
                bl[2 * p][0] = q0; bl[2 * p][1] = q1;
                bl[2 * p + 1][0] = q2; bl[2 * p + 1][1] = q3;
            }
#pragma unroll
            for (int mt = 0; mt < 2; mt++)
#pragma unroll
                for (int nt = 0; nt < 8; nt++)
                    MMA_BF16(accx[mt][nt], ah[mt], bh[nt]);
#pragma unroll
            for (int mt = 0; mt < 2; mt++)
#pragma unroll
                for (int nt = 0; nt < 8; nt++)
                    MMA_BF16(accx[mt][nt], ah[mt], bl[nt]);
#pragma unroll
            for (int mt = 0; mt < 2; mt++)
#pragma unroll
                for (int nt = 0; nt < 8; nt++)
                    MMA_BF16(accx[mt][nt], al[mt], bh[nt]);
#pragma unroll
            for (int mt = 0; mt < 2; mt++) {
                uint32_t ad = S + 2 * XT + arow_off + (uint32_t)(mt * 16 * 80);
                LDSM_X4(ah[mt][0], ah[mt][1], ah[mt][2], ah[mt][3], ad);
                LDSM_X4(al[mt][0], al[mt][1], al[mt][2], al[mt][3], ad + XT);
            }
#pragma unroll
            for (int p = 0; p < 4; p++) {
                uint32_t bd = S + 6 * XT + brow_off + (uint32_t)(p * 16 * 80);
                uint32_t q0, q1, q2, q3;
                LDSM_X4(q0, q1, q2, q3, bd);
                bh[2 * p][0] = q0; bh[2 * p][1] = q1;
                bh[2 * p + 1][0] = q2; bh[2 * p + 1][1] = q3;
                LDSM_X4(q0, q1, q2, q3, bd + XT);
                bl[2 * p][0] = q0; bl[2 * p][1] = q1;
                bl[2 * p + 1][0] = q2; bl[2 * p + 1][1] = q3;
            }
#pragma unroll
            for (int mt = 0; mt < 2; mt++)
#pragma unroll
                for (int nt = 0; nt < 8; nt++)
                    MMA_BF16(accy[mt][nt], ah[mt], bh[nt]);
#pragma unroll
            for (int mt = 0; mt < 2; mt++)
#pragma unroll
                for (int nt = 0; nt < 8; nt++)
                    MMA_BF16(accy[mt][nt], ah[mt], bl[nt]);
#pragma unroll
            for (int mt = 0; mt < 2; mt++)
#pragma unroll
                for (int nt = 0; nt < 8; nt++)
                    MMA_BF16(accy[mt][nt], al[mt], bh[nt]);
        }
        __syncthreads();
    }

    int tr = lane >> 2;
    int tc = (lane & 3) * 2;
#pragma unroll
    for (int mt = 0; mt < 2; mt++) {
        int row = m0 + warp_m * 32 + mt * 16 + tr;
#pragma unroll
        for (int nt = 0; nt < 8; nt++) {
            int col = n0 + warp_n * 64 + nt * 8 + tc;
            size_t i0 = (size_t)row * NN + col;
            size_t i1 = (size_t)(row + 8) * NN + col;
            float g0 = fmaxf(accx[mt][nt][0], 0.f) * fmaxf(accy[mt][nt][0], 0.f);
            float g1 = fmaxf(accx[mt][nt][1], 0.f) * fmaxf(accy[mt][nt][1], 0.f);
            float g2 = fmaxf(accx[mt][nt][2], 0.f) * fmaxf(accy[mt][nt][2], 0.f);
            float g3 = fmaxf(accx[mt][nt][3], 0.f) * fmaxf(accy[mt][nt][3], 0.f);
            __nv_bfloat16 h0, l0, h1, l1;
            split2(g0, h0, l0); split2(g1, h1, l1);
            *(__nv_bfloat162*)(Yhi + i0) = __halves2bfloat162(h0, h1);
            *(__nv_bfloat162*)(Ylo + i0) = __halves2bfloat162(l0, l1);
            split2(g2, h0, l0); split2(g3, h1, l1);
            *(__nv_bfloat162*)(Yhi + i1) = __halves2bfloat162(h0, h1);
            *(__nv_bfloat162*)(Ylo + i1) = __halves2bfloat162(l0, l1);
        }
    }
}

// ---------------- HMMA GEMM, cp.async double-buffered, optional split-K -----
#define TILE_B 18432
#define STAGE_B (4 * TILE_B)
#define TCG_SMEM (2 * STAGE_B)
__global__ void __launch_bounds__(256, 1)
tc_gemm(const __nv_bfloat16* __restrict__ Ahi, const __nv_bfloat16* __restrict__ Alo,
        const __nv_bfloat16* __restrict__ Bhi, const __nv_bfloat16* __restrict__ Blo,
        int Kslice, int lda, int ldb,
        float* __restrict__ C, int ldc, size_t cstride) {
    char* smc = dynsm;
    uint32_t sb = smem_u32(smc);

    int tid = threadIdx.x;
    int wid = tid >> 5;
    int lane = tid & 31;
    int warp_m = wid & 3;
    int warp_n = wid >> 2;

    int m0 = blockIdx.y * 128;
    int n0 = blockIdx.x * 128;
    int koff = blockIdx.z * Kslice;
    C += (size_t)blockIdx.z * cstride;

    float acc[2][8][4] = {};

    uint32_t a_row_l = (uint32_t)(lane & 15);
    uint32_t a_col_l = (uint32_t)((lane >> 4) << 3);
    uint32_t b_row_l = (uint32_t)(((lane & 16) >> 1) + (lane & 7));
    uint32_t b_col_l = (uint32_t)(lane & 8);

    int lr[4], lcc[4];
#pragma unroll
    for (int q = 0; q < 4; q++) {
        int l = tid + q * 256;
        lr[q] = l >> 3;
        lcc[q] = l & 7;
    }

    int nchunks = Kslice >> 6;

    auto issue = [&](int st, int kc) {
        uint32_t sbase = sb + (uint32_t)st * STAGE_B;
#pragma unroll
        for (int q = 0; q < 4; q++) {
            int r = lr[q], c = lcc[q];
            uint32_t so = sbase + (uint32_t)(r * 144 + c * 16);
            size_t ga = (size_t)(m0 + r) * lda + koff + kc + c * 8;
            size_t gb = (size_t)(n0 + r) * ldb + koff + kc + c * 8;
            CP_ASYNC16(so + 0 * TILE_B, (const void*)(Ahi + ga));
            CP_ASYNC16(so + 1 * TILE_B, (const void*)(Alo + ga));
            CP_ASYNC16(so + 2 * TILE_B, (const void*)(Bhi + gb));
            CP_ASYNC16(so + 3 * TILE_B, (const void*)(Blo + gb));
        }
    };

    issue(0, 0);
    CP_COMMIT();

    for (int ch = 0; ch < nchunks; ch++) {
        if (ch + 1 < nchunks) {
            issue((ch + 1) & 1, (ch + 1) << 6);
            CP_COMMIT();
            CP_WAIT(1);
        } else {
            CP_WAIT(0);
        }
        __syncthreads();

        uint32_t sA = sb + (uint32_t)(ch & 1) * STAGE_B;
        uint32_t sB = sA + 2 * TILE_B;
#pragma unroll
        for (int ks = 0; ks < 4; ks++) {
            uint32_t ah[2][4], al[2][4];
#pragma unroll
            for (int mt = 0; mt < 2; mt++) {
                uint32_t ad = sA + (uint32_t)(warp_m * 32 + mt * 16 + a_row_l) * 144
                            + (uint32_t)(ks * 16 + a_col_l) * 2;
                LDSM_X4(ah[mt][0], ah[mt][1], ah[mt][2], ah[mt][3], ad);
                LDSM_X4(al[mt][0], al[mt][1], al[mt][2], al[mt][3], ad + TILE_B);
            }
            uint32_t bh[8][2], bl[8][2];
#pragma unroll
            for (int p = 0; p < 4; p++) {
                uint32_t bd = sB + (uint32_t)(warp_n * 64 + p * 16 + b_row_l) * 144
                            + (uint32_t)(ks * 16 + b_col_l) * 2;
                uint32_t q0, q1, q2, q3;
                LDSM_X4(q0, q1, q2, q3, bd);
                bh[2 * p][0] = q0; bh[2 * p][1] = q1;
                bh[2 * p + 1][0] = q2; bh[2 * p + 1][1] = q3;
                LDSM_X4(q0, q1, q2, q3, bd + TILE_B);
                bl[2 * p][0] = q0; bl[2 * p][1] = q1;
                bl[2 * p + 1][0] = q2; bl[2 * p + 1][1] = q3;
            }
#pragma unroll
            for (int mt = 0; mt < 2; mt++)
#pragma unroll
                for (int nt = 0; nt < 8; nt++)
                    MMA_BF16(acc[mt][nt], ah[mt], bh[nt]);
#pragma unroll
            for (int mt = 0; mt < 2; mt++)
#pragma unroll
                for (int nt = 0; nt < 8; nt++)
                    MMA_BF16(acc[mt][nt], ah[mt], bl[nt]);
#pragma unroll
            for (int mt = 0; mt < 2; mt++)
#pragma unroll
                for (int nt = 0; nt < 8; nt++)
                    MMA_BF16(acc[mt][nt], al[mt], bh[nt]);
        }
        __syncthreads();
    }

    int tr = lane >> 2;
    int tc = (lane & 3) * 2;
#pragma unroll
    for (int mt = 0; mt < 2; mt++) {
        int row = m0 + warp_m * 32 + mt * 16 + tr;
#pragma unroll
        for (int nt = 0; nt < 8; nt++) {
            int col = n0 + warp_n * 64 + nt * 8 + tc;
            *(float2*)&C[(size_t)row * ldc + col] =
                make_float2(acc[mt][nt][0], acc[mt][nt][1]);
            *(float2*)&C[(size_t)(row + 8) * ldc + col] =
                make_float2(acc[mt][nt][2], acc[mt][nt][3]);
        }
    }
}

// ---------------- launch -----------------------------------------------------
extern "C" void kernel_launch(void* const* d_in, const int* in_sizes, int n_in,
                              void* d_out, int out_size) {
    const int* idx = (const int*)d_in[0];
    const float* wte = (const float*)d_in[1];
    const float* encoder = (const float*)d_in[2];
    const float* dec_x = (const float*)d_in[3];
    const float* dec_y = (const float*)d_in[4];
    const float* readout = (const float*)d_in[5];
    float* out = (float*)d_out;

    float *pv, *pR, *pH, *pup;
    __nv_bfloat16 *pvhi, *pvlo, *pRhi, *pRlo, *palnhi, *palnlo;
    __nv_bfloat16 *pwxhi, *pwxlo, *pwyhi, *pwylo, *penchi, *penclo, *prdhi, *prdlo;
    __nv_bfloat16 *pYhi, *pYlo, *pRThi, *pRTlo, *pVThi, *pVTlo, *pMhi, *pMlo;
    cudaGetSymbolAddress((void**)&pv, g_v);
    cudaGetSymbolAddress((void**)&pR, g_R);
    cudaGetSymbolAddress((void**)&pH, g_H);
    cudaGetSymbolAddress((void**)&pup, g_upart);
    cudaGetSymbolAddress((void**)&pvhi, g_vhi);
    cudaGetSymbolAddress((void**)&pvlo, g_vlo);
    cudaGetSymbolAddress((void**)&pRhi, g_Rhi);
    cudaGetSymbolAddress((void**)&pRlo, g_Rlo);
    cudaGetSymbolAddress((void**)&palnhi, g_alnhi);
    cudaGetSymbolAddress((void**)&palnlo, g_alnlo);
    cudaGetSymbolAddress((void**)&pwxhi, g_wxhi);
    cudaGetSymbolAddress((void**)&pwxlo, g_wxlo);
    cudaGetSymbolAddress((void**)&pwyhi, g_wyhi);
    cudaGetSymbolAddress((void**)&pwylo, g_wylo);
    cudaGetSymbolAddress((void**)&penchi, g_enchi);
    cudaGetSymbolAddress((void**)&penclo, g_enclo);
    cudaGetSymbolAddress((void**)&prdhi, g_rdhi);
    cudaGetSymbolAddress((void**)&prdlo, g_rdlo);
    cudaGetSymbolAddress((void**)&pYhi, g_Yhi);
    cudaGetSymbolAddress((void**)&pYlo, g_Ylo);
    cudaGetSymbolAddress((void**)&pRThi, g_RThi);
    cudaGetSymbolAddress((void**)&pRTlo, g_RTlo);
    cudaGetSymbolAddress((void**)&pVThi, g_VThi);
    cudaGetSymbolAddress((void**)&pVTlo, g_VTlo);
    cudaGetSymbolAddress((void**)&pMhi, g_Mhi);
    cudaGetSymbolAddress((void**)&pMlo, g_Mlo);

    cudaFuncSetAttribute(tc_gemm,
                         cudaFuncAttributeMaxDynamicSharedMemorySize, TCG_SMEM);
    cudaFuncSetAttribute(xy_gemm,
                         cudaFuncAttributeMaxDynamicSharedMemorySize, XY_SMEM);
    cudaFuncSetAttribute(kv_outer_kernel,
                         cudaFuncAttributeMaxDynamicSharedMemorySize, KVO_SMEM);
    cudaFuncSetAttribute(attn_out_kernel,
                         cudaFuncAttributeMaxDynamicSharedMemorySize, AO_SMEM);

    // launch #0
    embed_ln_rope_kernel<<<BT, 256>>>(idx, wte, pv, pvhi, pvlo, pR, pRhi, pRlo);
    // launch #1 (weights; needed before first xy)
    conv_all_kernel<<<24832, 256>>>(dec_x, dec_y, encoder, readout,
                                    pwxhi, pwxlo, pwyhi, pwylo,
                                    penchi, penclo, prdhi, prdlo);

    for (int layer = 0; layer < LL; layer++) {
        // launch #2 (layer 0): both transposes in one launch
        split_T_both_kernel<<<dim3(TT / 32, DD / 32, 2 * BB), 256>>>(
            pR, pv, pRThi, pRTlo, pVThi, pVTlo);
        // launch #3 (layer 0): profiled by ncu
        kv_outer_kernel<<<dim3(32, BB, 2), 512, KVO_SMEM>>>(pVThi, pVTlo,
                                                            pRThi, pRTlo, pH);
        prefix_split_kernel<<<dim3(256, BB), 256>>>(pH, pMhi, pMlo);
        attn_out_kernel<<<dim3(32, BB), 256, AO_SMEM>>>(pRhi, pRlo, pVThi, pVTlo,
                                                        pMhi, pMlo, palnhi, palnlo);
        // fused X/Y GEMM + gate -> Y hi/lo
        xy_gemm<<<dim3(NN / 128, BT / 128), 256, XY_SMEM>>>(
            pvhi, pvlo, palnhi, palnlo, pwxhi, pwxlo, pwyhi, pwylo, pYhi, pYlo);
        // u = Y @ encoder, split-K 4-way into partials
        tc_gemm<<<dim3(DD / 128, BT / 128, 4), 256, TCG_SMEM>>>(
            pYhi, pYlo, penchi, penclo, NN / 4, NN, NN, pup, DD, (size_t)BT * DD);
        // v += LN(sum partials); RoPE for next layer
        ln_add_rope_kernel<<<BT, 256>>>(pup, pv, pvhi, pvlo, pR, pRhi, pRlo);
    }

    // logits = v @ readout
    tc_gemm<<<dim3(VOCAB / 128, BT / 128, 1), 256, TCG_SMEM>>>(
        pvhi, pvlo, prdhi, prdlo, DD, DD, DD, out, VOCAB, 0);
}